// round 8
// baseline (speedup 1.0000x reference)
#include <cuda_runtime.h>
#include <math.h>
#include <stdint.h>

#define FIN 256
#define ND  16

// scratch (static device arrays — no allocations)
__device__ float g_Gr[FIN*ND];
__device__ float g_Gi[FIN*ND];
__device__ float g_A [FIN*ND];          // [k][n]
__device__ float g_c [ND];
__device__ float g_kw[9*ND];            // BN-folded depthwise weights [tap][d]
__device__ float g_kb[ND];              // BN-folded bias
__device__ float g_y [2*256*256*ND];    // intermediate y grid (8 MB)

__device__ __forceinline__ uint32_t smem_u32(const void* p) {
    uint32_t a;
    asm("{ .reg .u64 t; cvta.to.shared.u64 t, %1; cvt.u32.u64 %0, t; }"
        : "=r"(a) : "l"(p));
    return a;
}
__device__ __forceinline__ void mbar_init(uint32_t mbar, uint32_t count) {
    asm volatile("mbarrier.init.shared.b64 [%0], %1;" :: "r"(mbar), "r"(count) : "memory");
}
__device__ __forceinline__ void mbar_expect_tx(uint32_t mbar, uint32_t bytes) {
    asm volatile("mbarrier.arrive.expect_tx.shared.b64 _, [%0], %1;"
                 :: "r"(mbar), "r"(bytes) : "memory");
}
__device__ __forceinline__ void mbar_arrive(uint32_t mbar) {
    asm volatile("mbarrier.arrive.shared.b64 _, [%0];" :: "r"(mbar) : "memory");
}
__device__ __forceinline__ void mbar_wait(uint32_t mbar, uint32_t parity) {
    uint32_t done;
    asm volatile(
        "{\n\t"
        ".reg .pred p;\n\t"
        "mbarrier.try_wait.parity.acquire.cta.shared::cta.b64 p, [%1], %2;\n\t"
        "selp.b32 %0, 1, 0, p;\n\t"
        "}" : "=r"(done) : "r"(mbar), "r"(parity) : "memory");
    if (!done) {
        asm volatile(
            "{\n\t"
            ".reg .pred P1;\n\t"
            "WAIT_LOOP_%=:\n\t"
            "mbarrier.try_wait.parity.acquire.cta.shared::cta.b64 P1, [%0], %1, 0x989680;\n\t"
            "@P1 bra.uni WAIT_DONE_%=;\n\t"
            "bra.uni WAIT_LOOP_%=;\n\t"
            "WAIT_DONE_%=:\n\t"
            "}" :: "r"(mbar), "r"(parity) : "memory");
    }
}
// 1-D bulk async copy global -> shared (UBLKCP), completion via mbarrier tx bytes
__device__ __forceinline__ void bulk_g2s(uint32_t dst, const void* src,
                                         uint32_t bytes, uint32_t mbar) {
    asm volatile(
        "cp.async.bulk.shared::cluster.global.mbarrier::complete_tx::bytes "
        "[%0], [%1], %2, [%3];"
        :: "r"(dst), "l"(src), "r"(bytes), "r"(mbar) : "memory");
}

// ---------------------------------------------------------------------------
// pre1: G[k,d] = sum_m e^{-2pi i m k/256} (Wr[m,d] + i Wi[m,d])
// ---------------------------------------------------------------------------
__global__ void __launch_bounds__(256) pre1_kernel(const float* __restrict__ Wr,
                                                   const float* __restrict__ Wi)
{
    __shared__ float ct[256], st[256];
    int tid = threadIdx.x;
    {
        float ang = 6.283185307179586f * (float)tid / 256.0f;
        float s, c; sincosf(ang, &s, &c);
        ct[tid] = c; st[tid] = s;
    }
    __syncthreads();

    int i = blockIdx.x * 256 + tid;      // 0..4095
    int k = i >> 4, d = i & 15;
    float grA = 0.f, giA = 0.f, grB = 0.f, giB = 0.f;
#pragma unroll 4
    for (int m = 0; m < 256; m += 2) {
        int t0 = (m * k) & 255;
        int t1 = ((m + 1) * k) & 255;
        float c0 = ct[t0], s0 = st[t0];
        float c1 = ct[t1], s1 = st[t1];
        float wr0 = Wr[m * 16 + d],       wi0 = Wi[m * 16 + d];
        float wr1 = Wr[(m + 1) * 16 + d], wi1 = Wi[(m + 1) * 16 + d];
        grA = fmaf(c0, wr0, fmaf(s0, wi0, grA));
        giA = fmaf(c0, wi0, fmaf(-s0, wr0, giA));
        grB = fmaf(c1, wr1, fmaf(s1, wi1, grB));
        giB = fmaf(c1, wi1, fmaf(-s1, wr1, giB));
    }
    g_Gr[i] = grA + grB;
    g_Gi[i] = giA + giB;
}

// ---------------------------------------------------------------------------
// pre2: A[k,n] = (1/16) sum_d [Gr cos(2pi nd/16) - Gi sin(2pi nd/16)]
//       c[n], BN-folded conv weights/bias
// ---------------------------------------------------------------------------
__global__ void __launch_bounds__(256) pre2_kernel(const float* __restrict__ br,
                                                   const float* __restrict__ bi,
                                                   const float* __restrict__ dwk,
                                                   const float* __restrict__ dwb,
                                                   const float* __restrict__ gamma,
                                                   const float* __restrict__ beta,
                                                   const float* __restrict__ mmean,
                                                   const float* __restrict__ mvar)
{
    __shared__ float c16[16], s16[16];
    int tid = threadIdx.x;
    if (tid < 16) {
        float ang = 6.283185307179586f * (float)tid / 16.0f;
        float s, c; sincosf(ang, &s, &c);
        c16[tid] = c; s16[tid] = s;
    }
    __syncthreads();

    int i = blockIdx.x * 256 + tid;      // 0..4095
    int k = i >> 4, n = i & 15;
    float acc = 0.f;
#pragma unroll
    for (int d = 0; d < 16; d++) {
        int u = (n * d) & 15;
        acc = fmaf(g_Gr[k * 16 + d], c16[u], fmaf(-g_Gi[k * 16 + d], s16[u], acc));
    }
    g_A[k * 16 + n] = acc * 0.0625f;

    if (blockIdx.x == 0) {
        if (tid < 16) {
            float cc = 0.f;
#pragma unroll
            for (int d = 0; d < 16; d++) {
                int u = (tid * d) & 15;
                cc += (br[d] - bi[d]) * c16[u] - (br[d] + bi[d]) * s16[u];
            }
            g_c[tid] = cc * 0.0625f;
            float scale = gamma[tid] * rsqrtf(mvar[tid] + 1e-5f);
            g_kb[tid] = (dwb[tid] - mmean[tid]) * scale + beta[tid];
        }
        if (tid < 144) {
            int d = tid & 15;
            float scale = gamma[d] * rsqrtf(mvar[d] + 1e-5f);
            g_kw[tid] = dwk[tid] * scale;
        }
    }
}

// ---------------------------------------------------------------------------
// main GEMM: y[patch, n] = A[n,:] . p + c[n]
// Block = 128 thr = 4 warps = one (b, ph) patch row (256 patches).
// x rows are fetched with ONE cp.async.bulk per 16KB row (UBLKCP) into a
// 2-stage smem ring with full/empty mbarriers — removes the LSU 16B-per-
// instruction issue wall (~2.3 TB/s cap) that bound all previous rounds.
// Compute is the proven FFMA loop on the LINEAR row layout (conflict-free:
// each 8-lane LDS phase touches 2 distinct 16B chunks, 64B apart).
// Dynamic smem: xs[2][4096] + As[4096] + 4 mbarriers = 49184 B -> 4 blk/SM.
// ---------------------------------------------------------------------------
__global__ void __launch_bounds__(128) fno_gemm_kernel(const float* __restrict__ x)
{
    extern __shared__ __align__(128) float dsm[];
    float* xs0 = dsm;                    // 16 KB stage 0
    float* xs1 = dsm + 4096;             // 16 KB stage 1
    float* As  = dsm + 8192;             // 16 KB A matrix [k][16]
    uint32_t mb = smem_u32(dsm + 12288); // 4 x u64 mbarriers
    uint32_t full[2]  = { mb,      mb + 8  };
    uint32_t empty[2] = { mb + 16, mb + 24 };
    uint32_t xsa[2]   = { smem_u32(xs0), smem_u32(xs1) };
    float* xsp[2]     = { xs0, xs1 };

    int t    = threadIdx.x;
    int w    = t >> 5;
    int lane = t & 31;
    int bid  = blockIdx.x;               // b*256 + ph
    int b    = bid >> 8;
    int ph   = bid & 255;

    const float* xbase = x + (size_t)(b * 4096 + ph * 16) * 4096;

    if (t == 0) {
        mbar_init(full[0], 1);   mbar_init(full[1], 1);
        mbar_init(empty[0], 128); mbar_init(empty[1], 128);
        asm volatile("fence.proxy.async.shared::cta;" ::: "memory");
        // prefill stages 0,1 with rows 0,1
        mbar_expect_tx(full[0], 16384);
        bulk_g2s(xsa[0], xbase, 16384, full[0]);
        mbar_expect_tx(full[1], 16384);
        bulk_g2s(xsa[1], xbase + 4096, 16384, full[1]);
    }

    {   // stage A into smem (4096 floats) — overlaps with bulk copies
        const float4* A4  = (const float4*)g_A;
        float4*       As4 = (float4*)As;
#pragma unroll
        for (int it = 0; it < 8; it++)
            As4[t + it * 128] = A4[t + it * 128];
    }
    __syncthreads();                     // barriers initialized + As visible

    int cg = lane & 3;
    int pg = lane >> 2;                  // 0..7
    int pw = w * 64;                     // warp's first patch
    float4 acc[8];
#pragma unroll
    for (int jj = 0; jj < 8; jj++) acc[jj] = make_float4(0.f, 0.f, 0.f, 0.f);

    for (int kr = 0; kr < 16; kr++) {
        int st  = kr & 1;
        int phz = (kr >> 1) & 1;
        mbar_wait(full[st], phz);        // row kr data landed (acquire)

        const float* xb = xsp[st];
#pragma unroll
        for (int kc4 = 0; kc4 < 4; kc4++) {
            int k0 = kr * 16 + kc4 * 4;
            const float* Ab = &As[k0 * 16 + cg * 4];
            float4 A0 = *(const float4*)(Ab);
            float4 A1 = *(const float4*)(Ab + 16);
            float4 A2 = *(const float4*)(Ab + 32);
            float4 A3 = *(const float4*)(Ab + 48);
#pragma unroll
            for (int jj = 0; jj < 8; jj++) {
                int p = pw + jj * 8 + pg;       // patch 0..255
                float4 xv = *(const float4*)&xb[p * 16 + kc4 * 4];
                acc[jj].x = fmaf(xv.x, A0.x, fmaf(xv.y, A1.x, fmaf(xv.z, A2.x, fmaf(xv.w, A3.x, acc[jj].x))));
                acc[jj].y = fmaf(xv.x, A0.y, fmaf(xv.y, A1.y, fmaf(xv.z, A2.y, fmaf(xv.w, A3.y, acc[jj].y))));
                acc[jj].z = fmaf(xv.x, A0.z, fmaf(xv.y, A1.z, fmaf(xv.z, A2.z, fmaf(xv.w, A3.z, acc[jj].z))));
                acc[jj].w = fmaf(xv.x, A0.w, fmaf(xv.y, A1.w, fmaf(xv.z, A2.w, fmaf(xv.w, A3.w, acc[jj].w))));
            }
        }

        mbar_arrive(empty[st]);          // this thread done with stage st
        if (t == 0 && kr + 2 < 16) {
            mbar_wait(empty[st], phz);   // all 128 consumers done with use kr
            mbar_expect_tx(full[st], 16384);
            bulk_g2s(xsa[st], xbase + (size_t)(kr + 2) * 4096, 16384, full[st]);
        }
    }

    float4 cc = ((const float4*)g_c)[cg];
    float4* y4 = (float4*)g_y;
#pragma unroll
    for (int jj = 0; jj < 8; jj++) {
        int gp = bid * 256 + pw + jj * 8 + pg;   // global patch
        float4 o = acc[jj];
        o.x += cc.x; o.y += cc.y; o.z += cc.z; o.w += cc.w;
        y4[gp * 4 + cg] = o;
    }
}

// ---------------------------------------------------------------------------
// depthwise 3x3 SAME conv (BN folded) at resized positions.
// Two vertical outputs per thread: i = 2*iq and 2*iq+1 share row 4*iq+2.
// ---------------------------------------------------------------------------
__global__ void __launch_bounds__(128) conv_resize_kernel(float* __restrict__ out)
{
    int lin = blockIdx.x * 128 + threadIdx.x;   // 0..65535
    int cg = lin & 3;
    int j  = (lin >> 2) & 127;
    int iq = (lin >> 9) & 63;
    int b  = lin >> 15;

    int i0 = 2 * iq;
    int c1 = 2 * j + 1;
    int rbase = 4 * iq;                          // = (2*i0+1) - 1

    const float4* y4  = (const float4*)g_y;
    const float4* kw4 = (const float4*)g_kw;
    float4 kb = ((const float4*)g_kb)[cg];
    float4 s0 = kb, s1 = kb;

#pragma unroll
    for (int rr = 0; rr < 5; rr++) {
        int r = rbase + rr;
        if (r > 255) continue;                   // only rr=4 at iq=63
#pragma unroll
        for (int dx = -1; dx <= 1; dx++) {
            int c = c1 + dx;                     // c >= 0 always
            if (c > 255) continue;
            float4 v = y4[((b * 256 + r) * 256 + c) * 4 + cg];
            if (rr < 3) {                        // output i0: taps rows rr=0,1,2
                float4 w = kw4[(rr * 3 + (dx + 1)) * 4 + cg];
                s0.x = fmaf(v.x, w.x, s0.x);
                s0.y = fmaf(v.y, w.y, s0.y);
                s0.z = fmaf(v.z, w.z, s0.z);
                s0.w = fmaf(v.w, w.w, s0.w);
            }
            if (rr >= 2) {                       // output i0+1: taps rows rr=2,3,4
                float4 w = kw4[((rr - 2) * 3 + (dx + 1)) * 4 + cg];
                s1.x = fmaf(v.x, w.x, s1.x);
                s1.y = fmaf(v.y, w.y, s1.y);
                s1.z = fmaf(v.z, w.z, s1.z);
                s1.w = fmaf(v.w, w.w, s1.w);
            }
        }
    }
    float4* o4 = (float4*)out;
    o4[((b * 128 + i0) * 128 + j) * 4 + cg]       = s0;
    o4[((b * 128 + i0 + 1) * 128 + j) * 4 + cg]   = s1;
}

// ---------------------------------------------------------------------------
extern "C" void kernel_launch(void* const* d_in, const int* in_sizes, int n_in,
                              void* d_out, int out_size)
{
    const float* x     = (const float*)d_in[0];
    const float* Wr    = (const float*)d_in[1];
    const float* br    = (const float*)d_in[2];
    const float* Wi    = (const float*)d_in[3];
    const float* bi    = (const float*)d_in[4];
    const float* dwk   = (const float*)d_in[5];
    const float* dwb   = (const float*)d_in[6];
    const float* gamma = (const float*)d_in[7];
    const float* beta  = (const float*)d_in[8];
    const float* mmean = (const float*)d_in[9];
    const float* mvar  = (const float*)d_in[10];

    const int GEMM_SMEM = 49184;   // 2x16KB stages + 16KB A + mbarriers
    cudaFuncSetAttribute(fno_gemm_kernel,
                         cudaFuncAttributeMaxDynamicSharedMemorySize, GEMM_SMEM);
    cudaFuncSetAttribute(fno_gemm_kernel,
                         cudaFuncAttributePreferredSharedMemoryCarveout, 100);

    pre1_kernel<<<16, 256>>>(Wr, Wi);
    pre2_kernel<<<16, 256>>>(br, bi, dwk, dwb, gamma, beta, mmean, mvar);
    fno_gemm_kernel<<<512, 128, GEMM_SMEM>>>(x);
    conv_resize_kernel<<<512, 128>>>((float*)d_out);
}

// round 9
// speedup vs baseline: 1.0208x; 1.0208x over previous
#include <cuda_runtime.h>
#include <math.h>
#include <stdint.h>

#define FIN 256
#define ND  16

// scratch (static device arrays — no allocations)
__device__ float g_Gr[FIN*ND];
__device__ float g_Gi[FIN*ND];
__device__ float g_A [FIN*ND];          // [k][n]
__device__ float g_c [ND];
__device__ float g_kw[9*ND];            // BN-folded depthwise weights [tap][d]
__device__ float g_kb[ND];              // BN-folded bias
__device__ float g_y [2*256*256*ND];    // intermediate y grid (8 MB)

__device__ __forceinline__ uint32_t smem_u32(const void* p) {
    uint32_t a;
    asm("{ .reg .u64 t; cvta.to.shared.u64 t, %1; cvt.u32.u64 %0, t; }"
        : "=r"(a) : "l"(p));
    return a;
}
__device__ __forceinline__ void mbar_init(uint32_t mbar, uint32_t count) {
    asm volatile("mbarrier.init.shared.b64 [%0], %1;" :: "r"(mbar), "r"(count) : "memory");
}
__device__ __forceinline__ void mbar_expect_tx(uint32_t mbar, uint32_t bytes) {
    asm volatile("mbarrier.arrive.expect_tx.shared.b64 _, [%0], %1;"
                 :: "r"(mbar), "r"(bytes) : "memory");
}
__device__ __forceinline__ void mbar_arrive(uint32_t mbar) {
    asm volatile("mbarrier.arrive.shared.b64 _, [%0];" :: "r"(mbar) : "memory");
}
__device__ __forceinline__ void mbar_wait(uint32_t mbar, uint32_t parity) {
    uint32_t done;
    asm volatile(
        "{\n\t"
        ".reg .pred p;\n\t"
        "mbarrier.try_wait.parity.acquire.cta.shared::cta.b64 p, [%1], %2;\n\t"
        "selp.b32 %0, 1, 0, p;\n\t"
        "}" : "=r"(done) : "r"(mbar), "r"(parity) : "memory");
    if (!done) {
        asm volatile(
            "{\n\t"
            ".reg .pred P1;\n\t"
            "WAIT_LOOP_%=:\n\t"
            "mbarrier.try_wait.parity.acquire.cta.shared::cta.b64 P1, [%0], %1, 0x989680;\n\t"
            "@P1 bra.uni WAIT_DONE_%=;\n\t"
            "bra.uni WAIT_LOOP_%=;\n\t"
            "WAIT_DONE_%=:\n\t"
            "}" :: "r"(mbar), "r"(parity) : "memory");
    }
}
// 1-D bulk async copy global -> shared (UBLKCP), completion via mbarrier tx bytes
__device__ __forceinline__ void bulk_g2s(uint32_t dst, const void* src,
                                         uint32_t bytes, uint32_t mbar) {
    asm volatile(
        "cp.async.bulk.shared::cluster.global.mbarrier::complete_tx::bytes "
        "[%0], [%1], %2, [%3];"
        :: "r"(dst), "l"(src), "r"(bytes), "r"(mbar) : "memory");
}

// ---------------------------------------------------------------------------
// pre1: G[k,d] = sum_m e^{-2pi i m k/256} (Wr[m,d] + i Wi[m,d])
// ---------------------------------------------------------------------------
__global__ void __launch_bounds__(256) pre1_kernel(const float* __restrict__ Wr,
                                                   const float* __restrict__ Wi)
{
    __shared__ float ct[256], st[256];
    int tid = threadIdx.x;
    {
        float ang = 6.283185307179586f * (float)tid / 256.0f;
        float s, c; sincosf(ang, &s, &c);
        ct[tid] = c; st[tid] = s;
    }
    __syncthreads();

    int i = blockIdx.x * 256 + tid;      // 0..4095
    int k = i >> 4, d = i & 15;
    float grA = 0.f, giA = 0.f, grB = 0.f, giB = 0.f;
#pragma unroll 4
    for (int m = 0; m < 256; m += 2) {
        int t0 = (m * k) & 255;
        int t1 = ((m + 1) * k) & 255;
        float c0 = ct[t0], s0 = st[t0];
        float c1 = ct[t1], s1 = st[t1];
        float wr0 = Wr[m * 16 + d],       wi0 = Wi[m * 16 + d];
        float wr1 = Wr[(m + 1) * 16 + d], wi1 = Wi[(m + 1) * 16 + d];
        grA = fmaf(c0, wr0, fmaf(s0, wi0, grA));
        giA = fmaf(c0, wi0, fmaf(-s0, wr0, giA));
        grB = fmaf(c1, wr1, fmaf(s1, wi1, grB));
        giB = fmaf(c1, wi1, fmaf(-s1, wr1, giB));
    }
    g_Gr[i] = grA + grB;
    g_Gi[i] = giA + giB;
}

// ---------------------------------------------------------------------------
// pre2: A[k,n] = (1/16) sum_d [Gr cos(2pi nd/16) - Gi sin(2pi nd/16)]
//       c[n], BN-folded conv weights/bias
// ---------------------------------------------------------------------------
__global__ void __launch_bounds__(256) pre2_kernel(const float* __restrict__ br,
                                                   const float* __restrict__ bi,
                                                   const float* __restrict__ dwk,
                                                   const float* __restrict__ dwb,
                                                   const float* __restrict__ gamma,
                                                   const float* __restrict__ beta,
                                                   const float* __restrict__ mmean,
                                                   const float* __restrict__ mvar)
{
    __shared__ float c16[16], s16[16];
    int tid = threadIdx.x;
    if (tid < 16) {
        float ang = 6.283185307179586f * (float)tid / 16.0f;
        float s, c; sincosf(ang, &s, &c);
        c16[tid] = c; s16[tid] = s;
    }
    __syncthreads();

    int i = blockIdx.x * 256 + tid;      // 0..4095
    int k = i >> 4, n = i & 15;
    float acc = 0.f;
#pragma unroll
    for (int d = 0; d < 16; d++) {
        int u = (n * d) & 15;
        acc = fmaf(g_Gr[k * 16 + d], c16[u], fmaf(-g_Gi[k * 16 + d], s16[u], acc));
    }
    g_A[k * 16 + n] = acc * 0.0625f;

    if (blockIdx.x == 0) {
        if (tid < 16) {
            float cc = 0.f;
#pragma unroll
            for (int d = 0; d < 16; d++) {
                int u = (tid * d) & 15;
                cc += (br[d] - bi[d]) * c16[u] - (br[d] + bi[d]) * s16[u];
            }
            g_c[tid] = cc * 0.0625f;
            float scale = gamma[tid] * rsqrtf(mvar[tid] + 1e-5f);
            g_kb[tid] = (dwb[tid] - mmean[tid]) * scale + beta[tid];
        }
        if (tid < 144) {
            int d = tid & 15;
            float scale = gamma[d] * rsqrtf(mvar[d] + 1e-5f);
            g_kw[tid] = dwk[tid] * scale;
        }
    }
}

// ---------------------------------------------------------------------------
// main GEMM: y[patch, n] = A[n,:] . p + c[n]
// Block = 128 thr = 4 warps = one (b, ph) patch row (256 patches).
// 3-STAGE bulk-TMA ring (one UBLKCP per 16KB row), lookahead = 2 rows.
// empty barriers count = 4 (one elected arrive per warp) -> producer unblocks
// fast. A (16KB) read via LDG.128 (L1-hot, 4-lane dedup) -> no A smem stage.
// Dynamic smem: 3 x 16KB stages + 6 mbarriers = 49200 B -> 4 blocks/SM.
// ---------------------------------------------------------------------------
__global__ void __launch_bounds__(128) fno_gemm_kernel(const float* __restrict__ x)
{
    extern __shared__ __align__(128) float dsm[];
    uint32_t mb = smem_u32(dsm + 12288);      // barriers after 3 stages
    uint32_t xsa[3] = { smem_u32(dsm), smem_u32(dsm + 4096), smem_u32(dsm + 8192) };
    const float* xsp[3] = { dsm, dsm + 4096, dsm + 8192 };
    uint32_t full[3]  = { mb,      mb + 8,  mb + 16 };
    uint32_t empty[3] = { mb + 24, mb + 32, mb + 40 };

    int t    = threadIdx.x;
    int lane = t & 31;
    int bid  = blockIdx.x;               // b*256 + ph
    int b    = bid >> 8;
    int ph   = bid & 255;

    const float* xbase = x + (size_t)(b * 4096 + ph * 16) * 4096;

    if (t == 0) {
#pragma unroll
        for (int s = 0; s < 3; s++) {
            mbar_init(full[s], 1);
            mbar_init(empty[s], 4);
        }
        asm volatile("fence.proxy.async.shared::cta;" ::: "memory");
    }
    __syncthreads();                     // barriers visible before any poll

    if (t == 0) {                        // prefill stages 0..2 with rows 0..2
#pragma unroll
        for (int s = 0; s < 3; s++) {
            mbar_expect_tx(full[s], 16384);
            bulk_g2s(xsa[s], xbase + (size_t)s * 4096, 16384, full[s]);
        }
    }

    int w   = t >> 5;
    int cg  = lane & 3;
    int pg  = lane >> 2;                 // 0..7
    int pw  = w * 64;                    // warp's first patch
    const float4* A4 = (const float4*)g_A;    // frag: index k*4 + cg (L1-hot)

    float4 acc[8];
#pragma unroll
    for (int jj = 0; jj < 8; jj++) acc[jj] = make_float4(0.f, 0.f, 0.f, 0.f);

#pragma unroll 1
    for (int kr = 0; kr < 16; kr++) {
        int st  = kr % 3;
        int phz = (kr / 3) & 1;
        mbar_wait(full[st], phz);        // row kr landed (acquire)

        const float* xb = xsp[st];
#pragma unroll
        for (int kc4 = 0; kc4 < 4; kc4++) {
            int k0 = kr * 16 + kc4 * 4;
            float4 A0 = A4[(k0 + 0) * 4 + cg];
            float4 A1 = A4[(k0 + 1) * 4 + cg];
            float4 A2 = A4[(k0 + 2) * 4 + cg];
            float4 A3 = A4[(k0 + 3) * 4 + cg];
#pragma unroll
            for (int jj = 0; jj < 8; jj++) {
                int p = pw + jj * 8 + pg;       // patch 0..255
                float4 xv = *(const float4*)&xb[p * 16 + kc4 * 4];
                acc[jj].x = fmaf(xv.x, A0.x, fmaf(xv.y, A1.x, fmaf(xv.z, A2.x, fmaf(xv.w, A3.x, acc[jj].x))));
                acc[jj].y = fmaf(xv.x, A0.y, fmaf(xv.y, A1.y, fmaf(xv.z, A2.y, fmaf(xv.w, A3.y, acc[jj].y))));
                acc[jj].z = fmaf(xv.x, A0.z, fmaf(xv.y, A1.z, fmaf(xv.z, A2.z, fmaf(xv.w, A3.z, acc[jj].z))));
                acc[jj].w = fmaf(xv.x, A0.w, fmaf(xv.y, A1.w, fmaf(xv.z, A2.w, fmaf(xv.w, A3.w, acc[jj].w))));
            }
        }

        __syncwarp();
        if (lane == 0) mbar_arrive(empty[st]);   // warp done with stage st
        if (t == 0 && kr + 3 < 16) {
            mbar_wait(empty[st], phz);           // all 4 warps released st
            mbar_expect_tx(full[st], 16384);
            bulk_g2s(xsa[st], xbase + (size_t)(kr + 3) * 4096, 16384, full[st]);
        }
    }

    float4 cc = ((const float4*)g_c)[cg];
    float4* y4 = (float4*)g_y;
#pragma unroll
    for (int jj = 0; jj < 8; jj++) {
        int gp = bid * 256 + pw + jj * 8 + pg;   // global patch
        float4 o = acc[jj];
        o.x += cc.x; o.y += cc.y; o.z += cc.z; o.w += cc.w;
        y4[gp * 4 + cg] = o;
    }
}

// ---------------------------------------------------------------------------
// depthwise 3x3 SAME conv (BN folded) at resized positions.
// Two vertical outputs per thread: i = 2*iq and 2*iq+1 share row 4*iq+2.
// ---------------------------------------------------------------------------
__global__ void __launch_bounds__(128) conv_resize_kernel(float* __restrict__ out)
{
    int lin = blockIdx.x * 128 + threadIdx.x;   // 0..65535
    int cg = lin & 3;
    int j  = (lin >> 2) & 127;
    int iq = (lin >> 9) & 63;
    int b  = lin >> 15;

    int i0 = 2 * iq;
    int c1 = 2 * j + 1;
    int rbase = 4 * iq;                          // = (2*i0+1) - 1

    const float4* y4  = (const float4*)g_y;
    const float4* kw4 = (const float4*)g_kw;
    float4 kb = ((const float4*)g_kb)[cg];
    float4 s0 = kb, s1 = kb;

#pragma unroll
    for (int rr = 0; rr < 5; rr++) {
        int r = rbase + rr;
        if (r > 255) continue;                   // only rr=4 at iq=63
#pragma unroll
        for (int dx = -1; dx <= 1; dx++) {
            int c = c1 + dx;                     // c >= 0 always
            if (c > 255) continue;
            float4 v = y4[((b * 256 + r) * 256 + c) * 4 + cg];
            if (rr < 3) {                        // output i0: taps rows rr=0,1,2
                float4 w = kw4[(rr * 3 + (dx + 1)) * 4 + cg];
                s0.x = fmaf(v.x, w.x, s0.x);
                s0.y = fmaf(v.y, w.y, s0.y);
                s0.z = fmaf(v.z, w.z, s0.z);
                s0.w = fmaf(v.w, w.w, s0.w);
            }
            if (rr >= 2) {                       // output i0+1: taps rows rr=2,3,4
                float4 w = kw4[((rr - 2) * 3 + (dx + 1)) * 4 + cg];
                s1.x = fmaf(v.x, w.x, s1.x);
                s1.y = fmaf(v.y, w.y, s1.y);
                s1.z = fmaf(v.z, w.z, s1.z);
                s1.w = fmaf(v.w, w.w, s1.w);
            }
        }
    }
    float4* o4 = (float4*)out;
    o4[((b * 128 + i0) * 128 + j) * 4 + cg]       = s0;
    o4[((b * 128 + i0 + 1) * 128 + j) * 4 + cg]   = s1;
}

// ---------------------------------------------------------------------------
extern "C" void kernel_launch(void* const* d_in, const int* in_sizes, int n_in,
                              void* d_out, int out_size)
{
    const float* x     = (const float*)d_in[0];
    const float* Wr    = (const float*)d_in[1];
    const float* br    = (const float*)d_in[2];
    const float* Wi    = (const float*)d_in[3];
    const float* bi    = (const float*)d_in[4];
    const float* dwk   = (const float*)d_in[5];
    const float* dwb   = (const float*)d_in[6];
    const float* gamma = (const float*)d_in[7];
    const float* beta  = (const float*)d_in[8];
    const float* mmean = (const float*)d_in[9];
    const float* mvar  = (const float*)d_in[10];

    const int GEMM_SMEM = 49248;   // 3x16KB stages + mbarriers
    cudaFuncSetAttribute(fno_gemm_kernel,
                         cudaFuncAttributeMaxDynamicSharedMemorySize, GEMM_SMEM);
    cudaFuncSetAttribute(fno_gemm_kernel,
                         cudaFuncAttributePreferredSharedMemoryCarveout, 100);

    pre1_kernel<<<16, 256>>>(Wr, Wi);
    pre2_kernel<<<16, 256>>>(br, bi, dwk, dwb, gamma, beta, mmean, mvar);
    fno_gemm_kernel<<<512, 128, GEMM_SMEM>>>(x);
    conv_resize_kernel<<<512, 128>>>((float*)d_out);
}

// round 10
// speedup vs baseline: 1.1568x; 1.1332x over previous
#include <cuda_runtime.h>
#include <math.h>
#include <stdint.h>

#define FIN 256
#define ND  16

// scratch (static device arrays — no allocations)
__device__ float g_Gr[FIN*ND];
__device__ float g_Gi[FIN*ND];
__device__ float g_A [FIN*ND];          // [k][n]
__device__ float g_c [ND];
__device__ float g_kw[9*ND];            // BN-folded depthwise weights [tap][d]
__device__ float g_kb[ND];              // BN-folded bias
__device__ float g_y [2*256*256*ND];    // intermediate y grid (8 MB)

__device__ __forceinline__ uint32_t smem_u32(const void* p) {
    uint32_t a;
    asm("{ .reg .u64 t; cvta.to.shared.u64 t, %1; cvt.u32.u64 %0, t; }"
        : "=r"(a) : "l"(p));
    return a;
}
__device__ __forceinline__ void cp_async16(uint32_t dst, const void* src) {
    asm volatile("cp.async.cg.shared.global [%0], [%1], 16;" :: "r"(dst), "l"(src));
}

// ---------------------------------------------------------------------------
// pre1: G[k,d] = sum_m e^{-2pi i m k/256} (Wr[m,d] + i Wi[m,d])
// ---------------------------------------------------------------------------
__global__ void __launch_bounds__(256) pre1_kernel(const float* __restrict__ Wr,
                                                   const float* __restrict__ Wi)
{
    __shared__ float ct[256], st[256];
    int tid = threadIdx.x;
    {
        float ang = 6.283185307179586f * (float)tid / 256.0f;
        float s, c; sincosf(ang, &s, &c);
        ct[tid] = c; st[tid] = s;
    }
    __syncthreads();

    int i = blockIdx.x * 256 + tid;      // 0..4095
    int k = i >> 4, d = i & 15;
    float grA = 0.f, giA = 0.f, grB = 0.f, giB = 0.f;
#pragma unroll 4
    for (int m = 0; m < 256; m += 2) {
        int t0 = (m * k) & 255;
        int t1 = ((m + 1) * k) & 255;
        float c0 = ct[t0], s0 = st[t0];
        float c1 = ct[t1], s1 = st[t1];
        float wr0 = Wr[m * 16 + d],       wi0 = Wi[m * 16 + d];
        float wr1 = Wr[(m + 1) * 16 + d], wi1 = Wi[(m + 1) * 16 + d];
        grA = fmaf(c0, wr0, fmaf(s0, wi0, grA));
        giA = fmaf(c0, wi0, fmaf(-s0, wr0, giA));
        grB = fmaf(c1, wr1, fmaf(s1, wi1, grB));
        giB = fmaf(c1, wi1, fmaf(-s1, wr1, giB));
    }
    g_Gr[i] = grA + grB;
    g_Gi[i] = giA + giB;
}

// ---------------------------------------------------------------------------
// pre2: A[k,n] = (1/16) sum_d [Gr cos(2pi nd/16) - Gi sin(2pi nd/16)]
//       c[n], BN-folded conv weights/bias
// ---------------------------------------------------------------------------
__global__ void __launch_bounds__(256) pre2_kernel(const float* __restrict__ br,
                                                   const float* __restrict__ bi,
                                                   const float* __restrict__ dwk,
                                                   const float* __restrict__ dwb,
                                                   const float* __restrict__ gamma,
                                                   const float* __restrict__ beta,
                                                   const float* __restrict__ mmean,
                                                   const float* __restrict__ mvar)
{
    __shared__ float c16[16], s16[16];
    int tid = threadIdx.x;
    if (tid < 16) {
        float ang = 6.283185307179586f * (float)tid / 16.0f;
        float s, c; sincosf(ang, &s, &c);
        c16[tid] = c; s16[tid] = s;
    }
    __syncthreads();

    int i = blockIdx.x * 256 + tid;      // 0..4095
    int k = i >> 4, n = i & 15;
    float acc = 0.f;
#pragma unroll
    for (int d = 0; d < 16; d++) {
        int u = (n * d) & 15;
        acc = fmaf(g_Gr[k * 16 + d], c16[u], fmaf(-g_Gi[k * 16 + d], s16[u], acc));
    }
    g_A[k * 16 + n] = acc * 0.0625f;

    if (blockIdx.x == 0) {
        if (tid < 16) {
            float cc = 0.f;
#pragma unroll
            for (int d = 0; d < 16; d++) {
                int u = (tid * d) & 15;
                cc += (br[d] - bi[d]) * c16[u] - (br[d] + bi[d]) * s16[u];
            }
            g_c[tid] = cc * 0.0625f;
            float scale = gamma[tid] * rsqrtf(mvar[tid] + 1e-5f);
            g_kb[tid] = (dwb[tid] - mmean[tid]) * scale + beta[tid];
        }
        if (tid < 144) {
            int d = tid & 15;
            float scale = gamma[d] * rsqrtf(mvar[d] + 1e-5f);
            g_kw[tid] = dwk[tid] * scale;
        }
    }
}

// ---------------------------------------------------------------------------
// main GEMM: y[patch, n] = A[n,:] . p + c[n]
// R4's per-warp engine, repackaged for load balance:
//   grid = 1024 blocks (b, ph, half) x 64 threads (2 warps).
//   warp owns 64 patches; private 2x4KB cp.async double-buffer; XOR swizzle;
//   no block barriers anywhere (only __syncwarp per row).
//   A read via LDG.128 from g_A (16KB, L1-hot, 4-lane coalescer dedup) -> no
//   As smem stage. smem = 16KB/block -> 8 blocks/SM residentable -> all 1024
//   blocks co-resident, per-SM block count 7 vs 6 (1% imbalance vs 16% @R4).
// lane: cg = lane&3 (4 n-values), pg = lane>>2; patches p_local = jj*8+pg.
// ---------------------------------------------------------------------------
__global__ void __launch_bounds__(64, 8) fno_gemm_kernel(const float* __restrict__ x)
{
    __shared__ float xs[2][2][1024];     // [warp][buf][64 patches * 16 floats]

    int t    = threadIdx.x;
    int w    = t >> 5;
    int lane = t & 31;
    int bid  = blockIdx.x;               // b*512 + ph*2 + half
    int b    = bid >> 9;
    int ph   = (bid >> 1) & 255;
    int half = bid & 1;
    int pbase = half * 128 + w * 64;     // warp's first patch within the row

    // this warp's slice of the image row: 64 patches * 16 floats = 1024 floats
    const float* xbase = x + (size_t)(b * 4096 + ph * 16) * 4096 + pbase * 16;

    uint32_t buf[2] = { smem_u32(&xs[w][0][0]), smem_u32(&xs[w][1][0]) };
    uint32_t dstoff[8];
#pragma unroll
    for (int it = 0; it < 8; it++) {
        int g4 = lane + it * 32;         // chunk index within warp slice 0..255
        int p  = g4 >> 2, c = g4 & 3;
        int cc = c ^ ((p >> 1) & 3);
        dstoff[it] = (uint32_t)((p * 4 + cc) << 4);
    }

    // kick off row 0
    {
        const char* src = (const char*)xbase;
#pragma unroll
        for (int it = 0; it < 8; it++)
            cp_async16(buf[0] + dstoff[it], src + ((lane + it * 32) << 4));
        asm volatile("cp.async.commit_group;");
    }

    int cg  = lane & 3;
    int pg  = lane >> 2;                 // 0..7
    int swz = (pg >> 1) & 3;             // read-side swizzle key
    const float4* A4 = (const float4*)g_A;    // frag: index k*4 + cg (L1-hot)

    float4 acc[8];
#pragma unroll
    for (int jj = 0; jj < 8; jj++) acc[jj] = make_float4(0.f, 0.f, 0.f, 0.f);

    for (int kr = 0; kr < 16; kr++) {
        if (kr < 15) {
            uint32_t dbuf = buf[(kr + 1) & 1];
            const char* src = (const char*)(xbase + (size_t)(kr + 1) * 4096);
#pragma unroll
            for (int it = 0; it < 8; it++)
                cp_async16(dbuf + dstoff[it], src + ((lane + it * 32) << 4));
            asm volatile("cp.async.commit_group;");
            asm volatile("cp.async.wait_group 1;");   // row kr landed
        } else {
            asm volatile("cp.async.wait_group 0;");
        }
        __syncwarp();                    // all lanes' chunks of row kr visible

        const float* xb = xs[w][kr & 1];
#pragma unroll
        for (int kc4 = 0; kc4 < 4; kc4++) {
            int k0 = kr * 16 + kc4 * 4;
            float4 A0 = A4[(k0 + 0) * 4 + cg];
            float4 A1 = A4[(k0 + 1) * 4 + cg];
            float4 A2 = A4[(k0 + 2) * 4 + cg];
            float4 A3 = A4[(k0 + 3) * 4 + cg];
            int co = (kc4 ^ swz) << 2;   // swizzled float offset within patch
#pragma unroll
            for (int jj = 0; jj < 8; jj++) {
                int p = jj * 8 + pg;     // local patch 0..63
                float4 xv = *(const float4*)&xb[p * 16 + co];
                acc[jj].x = fmaf(xv.x, A0.x, fmaf(xv.y, A1.x, fmaf(xv.z, A2.x, fmaf(xv.w, A3.x, acc[jj].x))));
                acc[jj].y = fmaf(xv.x, A0.y, fmaf(xv.y, A1.y, fmaf(xv.z, A2.y, fmaf(xv.w, A3.y, acc[jj].y))));
                acc[jj].z = fmaf(xv.x, A0.z, fmaf(xv.y, A1.z, fmaf(xv.z, A2.z, fmaf(xv.w, A3.z, acc[jj].z))));
                acc[jj].w = fmaf(xv.x, A0.w, fmaf(xv.y, A1.w, fmaf(xv.z, A2.w, fmaf(xv.w, A3.w, acc[jj].w))));
            }
        }
        __syncwarp();                    // buffer (kr&1) free before re-issue at kr+1
    }

    float4 cc = ((const float4*)g_c)[cg];
    float4* y4 = (float4*)g_y;
#pragma unroll
    for (int jj = 0; jj < 8; jj++) {
        int gp = (b * 256 + ph) * 256 + pbase + jj * 8 + pg;   // global patch
        float4 o = acc[jj];
        o.x += cc.x; o.y += cc.y; o.z += cc.z; o.w += cc.w;
        y4[gp * 4 + cg] = o;
    }
}

// ---------------------------------------------------------------------------
// depthwise 3x3 SAME conv (BN folded) at resized positions.
// Two vertical outputs per thread: i = 2*iq and 2*iq+1 share row 4*iq+2.
// ---------------------------------------------------------------------------
__global__ void __launch_bounds__(128) conv_resize_kernel(float* __restrict__ out)
{
    int lin = blockIdx.x * 128 + threadIdx.x;   // 0..65535
    int cg = lin & 3;
    int j  = (lin >> 2) & 127;
    int iq = (lin >> 9) & 63;
    int b  = lin >> 15;

    int i0 = 2 * iq;
    int c1 = 2 * j + 1;
    int rbase = 4 * iq;                          // = (2*i0+1) - 1

    const float4* y4  = (const float4*)g_y;
    const float4* kw4 = (const float4*)g_kw;
    float4 kb = ((const float4*)g_kb)[cg];
    float4 s0 = kb, s1 = kb;

#pragma unroll
    for (int rr = 0; rr < 5; rr++) {
        int r = rbase + rr;
        if (r > 255) continue;                   // only rr=4 at iq=63
#pragma unroll
        for (int dx = -1; dx <= 1; dx++) {
            int c = c1 + dx;                     // c >= 0 always
            if (c > 255) continue;
            float4 v = y4[((b * 256 + r) * 256 + c) * 4 + cg];
            if (rr < 3) {                        // output i0: taps rows rr=0,1,2
                float4 w = kw4[(rr * 3 + (dx + 1)) * 4 + cg];
                s0.x = fmaf(v.x, w.x, s0.x);
                s0.y = fmaf(v.y, w.y, s0.y);
                s0.z = fmaf(v.z, w.z, s0.z);
                s0.w = fmaf(v.w, w.w, s0.w);
            }
            if (rr >= 2) {                       // output i0+1: taps rows rr=2,3,4
                float4 w = kw4[((rr - 2) * 3 + (dx + 1)) * 4 + cg];
                s1.x = fmaf(v.x, w.x, s1.x);
                s1.y = fmaf(v.y, w.y, s1.y);
                s1.z = fmaf(v.z, w.z, s1.z);
                s1.w = fmaf(v.w, w.w, s1.w);
            }
        }
    }
    float4* o4 = (float4*)out;
    o4[((b * 128 + i0) * 128 + j) * 4 + cg]       = s0;
    o4[((b * 128 + i0 + 1) * 128 + j) * 4 + cg]   = s1;
}

// ---------------------------------------------------------------------------
extern "C" void kernel_launch(void* const* d_in, const int* in_sizes, int n_in,
                              void* d_out, int out_size)
{
    const float* x     = (const float*)d_in[0];
    const float* Wr    = (const float*)d_in[1];
    const float* br    = (const float*)d_in[2];
    const float* Wi    = (const float*)d_in[3];
    const float* bi    = (const float*)d_in[4];
    const float* dwk   = (const float*)d_in[5];
    const float* dwb   = (const float*)d_in[6];
    const float* gamma = (const float*)d_in[7];
    const float* beta  = (const float*)d_in[8];
    const float* mmean = (const float*)d_in[9];
    const float* mvar  = (const float*)d_in[10];

    cudaFuncSetAttribute(fno_gemm_kernel,
                         cudaFuncAttributePreferredSharedMemoryCarveout, 100);

    pre1_kernel<<<16, 256>>>(Wr, Wi);
    pre2_kernel<<<16, 256>>>(br, bi, dwk, dwb, gamma, beta, mmean, mvar);
    fno_gemm_kernel<<<1024, 64>>>(x);
    conv_resize_kernel<<<512, 128>>>((float*)d_out);
}

// round 11
// speedup vs baseline: 1.1606x; 1.0033x over previous
#include <cuda_runtime.h>
#include <math.h>
#include <stdint.h>

#define FIN 256
#define ND  16

// scratch (static device arrays — no allocations)
__device__ float g_Gr[FIN*ND];
__device__ float g_Gi[FIN*ND];
__device__ float g_A [FIN*ND];          // [k][n]
__device__ float g_c [ND];
__device__ float g_kw[9*ND];            // BN-folded depthwise weights [tap][d]
__device__ float g_kb[ND];              // BN-folded bias
__device__ float g_y [2*256*256*ND];    // intermediate y grid (8 MB)

__device__ __forceinline__ uint32_t smem_u32(const void* p) {
    uint32_t a;
    asm("{ .reg .u64 t; cvta.to.shared.u64 t, %1; cvt.u32.u64 %0, t; }"
        : "=r"(a) : "l"(p));
    return a;
}
__device__ __forceinline__ void cp_async16(uint32_t dst, const void* src) {
    asm volatile("cp.async.cg.shared.global [%0], [%1], 16;" :: "r"(dst), "l"(src));
}

// ---------------------------------------------------------------------------
// pre1: G[k,d] = sum_m e^{-2pi i m k/256} (Wr[m,d] + i Wi[m,d])
// ---------------------------------------------------------------------------
__global__ void __launch_bounds__(256) pre1_kernel(const float* __restrict__ Wr,
                                                   const float* __restrict__ Wi)
{
    __shared__ float ct[256], st[256];
    int tid = threadIdx.x;
    {
        float ang = 6.283185307179586f * (float)tid / 256.0f;
        float s, c; sincosf(ang, &s, &c);
        ct[tid] = c; st[tid] = s;
    }
    __syncthreads();

    int i = blockIdx.x * 256 + tid;      // 0..4095
    int k = i >> 4, d = i & 15;
    float grA = 0.f, giA = 0.f, grB = 0.f, giB = 0.f;
#pragma unroll 4
    for (int m = 0; m < 256; m += 2) {
        int t0 = (m * k) & 255;
        int t1 = ((m + 1) * k) & 255;
        float c0 = ct[t0], s0 = st[t0];
        float c1 = ct[t1], s1 = st[t1];
        float wr0 = Wr[m * 16 + d],       wi0 = Wi[m * 16 + d];
        float wr1 = Wr[(m + 1) * 16 + d], wi1 = Wi[(m + 1) * 16 + d];
        grA = fmaf(c0, wr0, fmaf(s0, wi0, grA));
        giA = fmaf(c0, wi0, fmaf(-s0, wr0, giA));
        grB = fmaf(c1, wr1, fmaf(s1, wi1, grB));
        giB = fmaf(c1, wi1, fmaf(-s1, wr1, giB));
    }
    g_Gr[i] = grA + grB;
    g_Gi[i] = giA + giB;
}

// ---------------------------------------------------------------------------
// pre2: A[k,n] = (1/16) sum_d [Gr cos(2pi nd/16) - Gi sin(2pi nd/16)]
// ---------------------------------------------------------------------------
__global__ void __launch_bounds__(256) pre2_kernel()
{
    __shared__ float c16[16], s16[16];
    int tid = threadIdx.x;
    if (tid < 16) {
        float ang = 6.283185307179586f * (float)tid / 16.0f;
        float s, c; sincosf(ang, &s, &c);
        c16[tid] = c; s16[tid] = s;
    }
    __syncthreads();

    int i = blockIdx.x * 256 + tid;      // 0..4095
    int k = i >> 4, n = i & 15;
    float acc = 0.f;
#pragma unroll
    for (int d = 0; d < 16; d++) {
        int u = (n * d) & 15;
        acc = fmaf(g_Gr[k * 16 + d], c16[u], fmaf(-g_Gi[k * 16 + d], s16[u], acc));
    }
    g_A[k * 16 + n] = acc * 0.0625f;
}

// ---------------------------------------------------------------------------
// pre3: c[n] (folded complex-dense biases through IFFT), BN-folded depthwise
//       conv weights/bias. 1 block — also positions the gemm at the ncu
//       capture index (-s 5) so the NEXT profile shows the gemm, not conv.
// ---------------------------------------------------------------------------
__global__ void __launch_bounds__(160) pre3_kernel(const float* __restrict__ br,
                                                   const float* __restrict__ bi,
                                                   const float* __restrict__ dwk,
                                                   const float* __restrict__ dwb,
                                                   const float* __restrict__ gamma,
                                                   const float* __restrict__ beta,
                                                   const float* __restrict__ mmean,
                                                   const float* __restrict__ mvar)
{
    int tid = threadIdx.x;
    if (tid < 16) {
        float cc = 0.f;
#pragma unroll
        for (int d = 0; d < 16; d++) {
            float ang = 6.283185307179586f * (float)((tid * d) & 15) / 16.0f;
            float s, c; sincosf(ang, &s, &c);
            cc += (br[d] - bi[d]) * c - (br[d] + bi[d]) * s;
        }
        g_c[tid] = cc * 0.0625f;
        float scale = gamma[tid] * rsqrtf(mvar[tid] + 1e-5f);
        g_kb[tid] = (dwb[tid] - mmean[tid]) * scale + beta[tid];
    }
    if (tid < 144) {
        int d = tid & 15;
        float scale = gamma[d] * rsqrtf(mvar[d] + 1e-5f);
        g_kw[tid] = dwk[tid] * scale;
    }
}

// ---------------------------------------------------------------------------
// main GEMM: y[patch, n] = A[n,:] . p + c[n]   (identical to best round R4)
// block = 128 threads = 4 warps; warp w owns 64 contiguous patches.
// Per-warp PRIVATE 2x4KB cp.async double-buffer -> no __syncthreads in the
// mainloop; per-row sync is wait_group + __syncwarp only.
// lane: cg = lane&3 (4 n-values), pg = lane>>2; patches p_local = jj*8+pg.
// XOR swizzle: chunk(p,c) stored at p*4 + (c ^ ((p>>1)&3)); read key (pg>>1)&3.
// ---------------------------------------------------------------------------
__global__ void __launch_bounds__(128, 4) fno_gemm_kernel(const float* __restrict__ x)
{
    __shared__ float xs[4][2][1024];     // [warp][buf][64 patches * 16 floats]
    __shared__ float As[FIN * ND];       // A: [k][16]

    int t    = threadIdx.x;
    int w    = t >> 5;
    int lane = t & 31;
    int bid  = blockIdx.x;               // b*256 + ph
    int b    = bid >> 8;
    int ph   = bid & 255;

    // this warp's slice of the image row: 64 patches * 16 floats = 1024 floats
    const float* xbase = x + (size_t)(b * 4096 + ph * 16) * 4096 + w * 1024;

    uint32_t buf[2] = { smem_u32(&xs[w][0][0]), smem_u32(&xs[w][1][0]) };
    uint32_t dstoff[8];
#pragma unroll
    for (int it = 0; it < 8; it++) {
        int g4 = lane + it * 32;         // chunk index within warp slice 0..255
        int p  = g4 >> 2, c = g4 & 3;
        int cc = c ^ ((p >> 1) & 3);
        dstoff[it] = (uint32_t)((p * 4 + cc) << 4);
    }

    // kick off row 0
    {
        const char* src = (const char*)xbase;
#pragma unroll
        for (int it = 0; it < 8; it++)
            cp_async16(buf[0] + dstoff[it], src + ((lane + it * 32) << 4));
        asm volatile("cp.async.commit_group;");
    }

    {   // stage A into smem (4096 floats) — overlaps with row-0 cp.async
        const float4* A4  = (const float4*)g_A;
        float4*       As4 = (float4*)As;
#pragma unroll
        for (int it = 0; it < 8; it++)
            As4[t + it * 128] = A4[t + it * 128];
    }
    __syncthreads();                     // As visible to all warps (once, pre-loop)

    int cg  = lane & 3;
    int pg  = lane >> 2;                 // 0..7
    int swz = (pg >> 1) & 3;             // read-side swizzle key
    float4 acc[8];
#pragma unroll
    for (int jj = 0; jj < 8; jj++) acc[jj] = make_float4(0.f, 0.f, 0.f, 0.f);

    for (int kr = 0; kr < 16; kr++) {
        if (kr < 15) {
            uint32_t dbuf = buf[(kr + 1) & 1];
            const char* src = (const char*)(xbase + (size_t)(kr + 1) * 4096);
#pragma unroll
            for (int it = 0; it < 8; it++)
                cp_async16(dbuf + dstoff[it], src + ((lane + it * 32) << 4));
            asm volatile("cp.async.commit_group;");
            asm volatile("cp.async.wait_group 1;");   // row kr landed
        } else {
            asm volatile("cp.async.wait_group 0;");
        }
        __syncwarp();                    // all lanes' chunks of row kr visible

        const float* xb = xs[w][kr & 1];
#pragma unroll
        for (int kc4 = 0; kc4 < 4; kc4++) {
            int k0 = kr * 16 + kc4 * 4;
            const float* Ab = &As[k0 * 16 + cg * 4];
            float4 A0 = *(const float4*)(Ab);
            float4 A1 = *(const float4*)(Ab + 16);
            float4 A2 = *(const float4*)(Ab + 32);
            float4 A3 = *(const float4*)(Ab + 48);
            int co = (kc4 ^ swz) << 2;   // swizzled float offset within patch
#pragma unroll
            for (int jj = 0; jj < 8; jj++) {
                int p = jj * 8 + pg;     // local patch 0..63
                float4 xv = *(const float4*)&xb[p * 16 + co];
                acc[jj].x = fmaf(xv.x, A0.x, fmaf(xv.y, A1.x, fmaf(xv.z, A2.x, fmaf(xv.w, A3.x, acc[jj].x))));
                acc[jj].y = fmaf(xv.x, A0.y, fmaf(xv.y, A1.y, fmaf(xv.z, A2.y, fmaf(xv.w, A3.y, acc[jj].y))));
                acc[jj].z = fmaf(xv.x, A0.z, fmaf(xv.y, A1.z, fmaf(xv.z, A2.z, fmaf(xv.w, A3.z, acc[jj].z))));
                acc[jj].w = fmaf(xv.x, A0.w, fmaf(xv.y, A1.w, fmaf(xv.z, A2.w, fmaf(xv.w, A3.w, acc[jj].w))));
            }
        }
        __syncwarp();                    // buffer (kr&1) free before re-issue at kr+1
    }

    float4 cc = ((const float4*)g_c)[cg];
    float4* y4 = (float4*)g_y;
#pragma unroll
    for (int jj = 0; jj < 8; jj++) {
        int gp = bid * 256 + w * 64 + jj * 8 + pg;   // global patch
        float4 o = acc[jj];
        o.x += cc.x; o.y += cc.y; o.z += cc.z; o.w += cc.w;
        y4[gp * 4 + cg] = o;
    }
}

// ---------------------------------------------------------------------------
// depthwise 3x3 SAME conv (BN folded) at resized positions.
// Two vertical outputs per thread: i = 2*iq and 2*iq+1 share row 4*iq+2.
// ---------------------------------------------------------------------------
__global__ void __launch_bounds__(128) conv_resize_kernel(float* __restrict__ out)
{
    int lin = blockIdx.x * 128 + threadIdx.x;   // 0..65535
    int cg = lin & 3;
    int j  = (lin >> 2) & 127;
    int iq = (lin >> 9) & 63;
    int b  = lin >> 15;

    int i0 = 2 * iq;
    int c1 = 2 * j + 1;
    int rbase = 4 * iq;                          // = (2*i0+1) - 1

    const float4* y4  = (const float4*)g_y;
    const float4* kw4 = (const float4*)g_kw;
    float4 kb = ((const float4*)g_kb)[cg];
    float4 s0 = kb, s1 = kb;

#pragma unroll
    for (int rr = 0; rr < 5; rr++) {
        int r = rbase + rr;
        if (r > 255) continue;                   // only rr=4 at iq=63
#pragma unroll
        for (int dx = -1; dx <= 1; dx++) {
            int c = c1 + dx;                     // c >= 0 always
            if (c > 255) continue;
            float4 v = y4[((b * 256 + r) * 256 + c) * 4 + cg];
            if (rr < 3) {                        // output i0: taps rows rr=0,1,2
                float4 w = kw4[(rr * 3 + (dx + 1)) * 4 + cg];
                s0.x = fmaf(v.x, w.x, s0.x);
                s0.y = fmaf(v.y, w.y, s0.y);
                s0.z = fmaf(v.z, w.z, s0.z);
                s0.w = fmaf(v.w, w.w, s0.w);
            }
            if (rr >= 2) {                       // output i0+1: taps rows rr=2,3,4
                float4 w = kw4[((rr - 2) * 3 + (dx + 1)) * 4 + cg];
                s1.x = fmaf(v.x, w.x, s1.x);
                s1.y = fmaf(v.y, w.y, s1.y);
                s1.z = fmaf(v.z, w.z, s1.z);
                s1.w = fmaf(v.w, w.w, s1.w);
            }
        }
    }
    float4* o4 = (float4*)out;
    o4[((b * 128 + i0) * 128 + j) * 4 + cg]       = s0;
    o4[((b * 128 + i0 + 1) * 128 + j) * 4 + cg]   = s1;
}

// ---------------------------------------------------------------------------
extern "C" void kernel_launch(void* const* d_in, const int* in_sizes, int n_in,
                              void* d_out, int out_size)
{
    const float* x     = (const float*)d_in[0];
    const float* Wr    = (const float*)d_in[1];
    const float* br    = (const float*)d_in[2];
    const float* Wi    = (const float*)d_in[3];
    const float* bi    = (const float*)d_in[4];
    const float* dwk   = (const float*)d_in[5];
    const float* dwb   = (const float*)d_in[6];
    const float* gamma = (const float*)d_in[7];
    const float* beta  = (const float*)d_in[8];
    const float* mmean = (const float*)d_in[9];
    const float* mvar  = (const float*)d_in[10];

    pre1_kernel<<<16, 256>>>(Wr, Wi);
    pre2_kernel<<<16, 256>>>();
    pre3_kernel<<<1, 160>>>(br, bi, dwk, dwb, gamma, beta, mmean, mvar);
    fno_gemm_kernel<<<512, 128>>>(x);       // 4th launch -> ncu -s 5 capture slot
    conv_resize_kernel<<<512, 128>>>((float*)d_out);
}

// round 12
// speedup vs baseline: 1.5639x; 1.3475x over previous
#include <cuda_runtime.h>
#include <math.h>
#include <stdint.h>

#define FIN 256
#define ND  16

// scratch (static device arrays — no allocations)
__device__ float g_A [FIN*ND];          // [k][n]
__device__ float g_c [ND];
__device__ float g_kw[9*ND];            // BN-folded depthwise weights [tap][d]
__device__ float g_kb[ND];              // BN-folded bias
__device__ float g_y [2*256*256*ND];    // intermediate y grid (8 MB)

__device__ __forceinline__ uint32_t smem_u32(const void* p) {
    uint32_t a;
    asm("{ .reg .u64 t; cvta.to.shared.u64 t, %1; cvt.u32.u64 %0, t; }"
        : "=r"(a) : "l"(p));
    return a;
}
__device__ __forceinline__ void cp_async16(uint32_t dst, const void* src) {
    asm volatile("cp.async.cg.shared.global [%0], [%1], 16;" :: "r"(dst), "l"(src));
}

// ---------------------------------------------------------------------------
// pre (fused pre1+pre2+pre3):
//   G[k,d] = sum_m e^{-2pi i m k/256} (Wr[m,d] + i Wi[m,d])   [block-local k]
//   A[k,n] = (1/16) sum_d [Gr cos(2pi nd/16) - Gi sin(2pi nd/16)]
//   c[n], BN-folded conv weights/bias (block 0).
// Block bid covers k in [16*bid, 16*bid+16): G for those k lives entirely in
// this block -> keep it in smem, no interkernel roundtrip. 16 blocks x 256.
// ---------------------------------------------------------------------------
__global__ void __launch_bounds__(256) pre_kernel(const float* __restrict__ Wr,
                                                  const float* __restrict__ Wi,
                                                  const float* __restrict__ br,
                                                  const float* __restrict__ bi,
                                                  const float* __restrict__ dwk,
                                                  const float* __restrict__ dwb,
                                                  const float* __restrict__ gamma,
                                                  const float* __restrict__ beta,
                                                  const float* __restrict__ mmean,
                                                  const float* __restrict__ mvar)
{
    __shared__ float ct[256], st[256];
    __shared__ float gsr[256], gsi[256];   // block-local G: [k_local*16 + d]
    int tid = threadIdx.x;
    {
        float ang = 6.283185307179586f * (float)tid / 256.0f;
        float s, c; sincosf(ang, &s, &c);
        ct[tid] = c; st[tid] = s;
    }
    __syncthreads();

    int i = blockIdx.x * 256 + tid;      // 0..4095
    int k = i >> 4, d = i & 15;
    float grA = 0.f, giA = 0.f, grB = 0.f, giB = 0.f;
#pragma unroll 4
    for (int m = 0; m < 256; m += 2) {
        int t0 = (m * k) & 255;
        int t1 = ((m + 1) * k) & 255;
        float c0 = ct[t0], s0 = st[t0];
        float c1 = ct[t1], s1 = st[t1];
        float wr0 = Wr[m * 16 + d],       wi0 = Wi[m * 16 + d];
        float wr1 = Wr[(m + 1) * 16 + d], wi1 = Wi[(m + 1) * 16 + d];
        grA = fmaf(c0, wr0, fmaf(s0, wi0, grA));
        giA = fmaf(c0, wi0, fmaf(-s0, wr0, giA));
        grB = fmaf(c1, wr1, fmaf(s1, wi1, grB));
        giB = fmaf(c1, wi1, fmaf(-s1, wr1, giB));
    }
    gsr[tid] = grA + grB;
    gsi[tid] = giA + giB;
    __syncthreads();

    // pre2: A[k,n] from block-local G. tid -> same k, n = d slot.
    // cos(2pi u/16) = ct[16u], sin = st[16u].
    int n  = d;
    int kl = tid & ~15;                  // k_local * 16
    float acc = 0.f;
#pragma unroll
    for (int dd = 0; dd < 16; dd++) {
        int u = ((n * dd) & 15) << 4;
        acc = fmaf(gsr[kl + dd], ct[u], fmaf(-gsi[kl + dd], st[u], acc));
    }
    g_A[k * 16 + n] = acc * 0.0625f;

    // pre3: scalar folds (block 0 only; reuses ct/st, no sincosf)
    if (blockIdx.x == 0) {
        if (tid < 16) {
            float cc = 0.f;
#pragma unroll
            for (int dd = 0; dd < 16; dd++) {
                int u = ((tid * dd) & 15) << 4;
                cc += (br[dd] - bi[dd]) * ct[u] - (br[dd] + bi[dd]) * st[u];
            }
            g_c[tid] = cc * 0.0625f;
            float scale = gamma[tid] * rsqrtf(mvar[tid] + 1e-5f);
            g_kb[tid] = (dwb[tid] - mmean[tid]) * scale + beta[tid];
        }
        if (tid < 144) {
            int dd = tid & 15;
            float scale = gamma[dd] * rsqrtf(mvar[dd] + 1e-5f);
            g_kw[tid] = dwk[tid] * scale;
        }
    }
}

// ---------------------------------------------------------------------------
// main GEMM: y[patch, n] = A[n,:] . p + c[n]   (identical to best round R4)
// block = 128 threads = 4 warps; warp w owns 64 contiguous patches.
// Per-warp PRIVATE 2x4KB cp.async double-buffer -> no __syncthreads in the
// mainloop; per-row sync is wait_group + __syncwarp only.
// lane: cg = lane&3 (4 n-values), pg = lane>>2; patches p_local = jj*8+pg.
// XOR swizzle: chunk(p,c) stored at p*4 + (c ^ ((p>>1)&3)); read key (pg>>1)&3.
// Measured (R11 ncu): 32.8us = 100% scalar-FFMA-pipe rate.
// ---------------------------------------------------------------------------
__global__ void __launch_bounds__(128, 4) fno_gemm_kernel(const float* __restrict__ x)
{
    __shared__ float xs[4][2][1024];     // [warp][buf][64 patches * 16 floats]
    __shared__ float As[FIN * ND];       // A: [k][16]

    int t    = threadIdx.x;
    int w    = t >> 5;
    int lane = t & 31;
    int bid  = blockIdx.x;               // b*256 + ph
    int b    = bid >> 8;
    int ph   = bid & 255;

    // this warp's slice of the image row: 64 patches * 16 floats = 1024 floats
    const float* xbase = x + (size_t)(b * 4096 + ph * 16) * 4096 + w * 1024;

    uint32_t buf[2] = { smem_u32(&xs[w][0][0]), smem_u32(&xs[w][1][0]) };
    uint32_t dstoff[8];
#pragma unroll
    for (int it = 0; it < 8; it++) {
        int g4 = lane + it * 32;         // chunk index within warp slice 0..255
        int p  = g4 >> 2, c = g4 & 3;
        int cc = c ^ ((p >> 1) & 3);
        dstoff[it] = (uint32_t)((p * 4 + cc) << 4);
    }

    // kick off row 0
    {
        const char* src = (const char*)xbase;
#pragma unroll
        for (int it = 0; it < 8; it++)
            cp_async16(buf[0] + dstoff[it], src + ((lane + it * 32) << 4));
        asm volatile("cp.async.commit_group;");
    }

    {   // stage A into smem (4096 floats) — overlaps with row-0 cp.async
        const float4* A4  = (const float4*)g_A;
        float4*       As4 = (float4*)As;
#pragma unroll
        for (int it = 0; it < 8; it++)
            As4[t + it * 128] = A4[t + it * 128];
    }
    __syncthreads();                     // As visible to all warps (once, pre-loop)

    int cg  = lane & 3;
    int pg  = lane >> 2;                 // 0..7
    int swz = (pg >> 1) & 3;             // read-side swizzle key
    float4 acc[8];
#pragma unroll
    for (int jj = 0; jj < 8; jj++) acc[jj] = make_float4(0.f, 0.f, 0.f, 0.f);

    for (int kr = 0; kr < 16; kr++) {
        if (kr < 15) {
            uint32_t dbuf = buf[(kr + 1) & 1];
            const char* src = (const char*)(xbase + (size_t)(kr + 1) * 4096);
#pragma unroll
            for (int it = 0; it < 8; it++)
                cp_async16(dbuf + dstoff[it], src + ((lane + it * 32) << 4));
            asm volatile("cp.async.commit_group;");
            asm volatile("cp.async.wait_group 1;");   // row kr landed
        } else {
            asm volatile("cp.async.wait_group 0;");
        }
        __syncwarp();                    // all lanes' chunks of row kr visible

        const float* xb = xs[w][kr & 1];
#pragma unroll
        for (int kc4 = 0; kc4 < 4; kc4++) {
            int k0 = kr * 16 + kc4 * 4;
            const float* Ab = &As[k0 * 16 + cg * 4];
            float4 A0 = *(const float4*)(Ab);
            float4 A1 = *(const float4*)(Ab + 16);
            float4 A2 = *(const float4*)(Ab + 32);
            float4 A3 = *(const float4*)(Ab + 48);
            int co = (kc4 ^ swz) << 2;   // swizzled float offset within patch
#pragma unroll
            for (int jj = 0; jj < 8; jj++) {
                int p = jj * 8 + pg;     // local patch 0..63
                float4 xv = *(const float4*)&xb[p * 16 + co];
                acc[jj].x = fmaf(xv.x, A0.x, fmaf(xv.y, A1.x, fmaf(xv.z, A2.x, fmaf(xv.w, A3.x, acc[jj].x))));
                acc[jj].y = fmaf(xv.x, A0.y, fmaf(xv.y, A1.y, fmaf(xv.z, A2.y, fmaf(xv.w, A3.y, acc[jj].y))));
                acc[jj].z = fmaf(xv.x, A0.z, fmaf(xv.y, A1.z, fmaf(xv.z, A2.z, fmaf(xv.w, A3.z, acc[jj].z))));
                acc[jj].w = fmaf(xv.x, A0.w, fmaf(xv.y, A1.w, fmaf(xv.z, A2.w, fmaf(xv.w, A3.w, acc[jj].w))));
            }
        }
        __syncwarp();                    // buffer (kr&1) free before re-issue at kr+1
    }

    float4 cc = ((const float4*)g_c)[cg];
    float4* y4 = (float4*)g_y;
#pragma unroll
    for (int jj = 0; jj < 8; jj++) {
        int gp = bid * 256 + w * 64 + jj * 8 + pg;   // global patch
        float4 o = acc[jj];
        o.x += cc.x; o.y += cc.y; o.z += cc.z; o.w += cc.w;
        y4[gp * 4 + cg] = o;
    }
}

// ---------------------------------------------------------------------------
// depthwise 3x3 SAME conv (BN folded) at resized positions.
// Two vertical outputs per thread: i = 2*iq and 2*iq+1 share row 4*iq+2.
// ---------------------------------------------------------------------------
__global__ void __launch_bounds__(128) conv_resize_kernel(float* __restrict__ out)
{
    int lin = blockIdx.x * 128 + threadIdx.x;   // 0..65535
    int cg = lin & 3;
    int j  = (lin >> 2) & 127;
    int iq = (lin >> 9) & 63;
    int b  = lin >> 15;

    int i0 = 2 * iq;
    int c1 = 2 * j + 1;
    int rbase = 4 * iq;                          // = (2*i0+1) - 1

    const float4* y4  = (const float4*)g_y;
    const float4* kw4 = (const float4*)g_kw;
    float4 kb = ((const float4*)g_kb)[cg];
    float4 s0 = kb, s1 = kb;

#pragma unroll
    for (int rr = 0; rr < 5; rr++) {
        int r = rbase + rr;
        if (r > 255) continue;                   // only rr=4 at iq=63
#pragma unroll
        for (int dx = -1; dx <= 1; dx++) {
            int c = c1 + dx;                     // c >= 0 always
            if (c > 255) continue;
            float4 v = y4[((b * 256 + r) * 256 + c) * 4 + cg];
            if (rr < 3) {                        // output i0: taps rows rr=0,1,2
                float4 w = kw4[(rr * 3 + (dx + 1)) * 4 + cg];
                s0.x = fmaf(v.x, w.x, s0.x);
                s0.y = fmaf(v.y, w.y, s0.y);
                s0.z = fmaf(v.z, w.z, s0.z);
                s0.w = fmaf(v.w, w.w, s0.w);
            }
            if (rr >= 2) {                       // output i0+1: taps rows rr=2,3,4
                float4 w = kw4[((rr - 2) * 3 + (dx + 1)) * 4 + cg];
                s1.x = fmaf(v.x, w.x, s1.x);
                s1.y = fmaf(v.y, w.y, s1.y);
                s1.z = fmaf(v.z, w.z, s1.z);
                s1.w = fmaf(v.w, w.w, s1.w);
            }
        }
    }
    float4* o4 = (float4*)out;
    o4[((b * 128 + i0) * 128 + j) * 4 + cg]       = s0;
    o4[((b * 128 + i0 + 1) * 128 + j) * 4 + cg]   = s1;
}

// ---------------------------------------------------------------------------
extern "C" void kernel_launch(void* const* d_in, const int* in_sizes, int n_in,
                              void* d_out, int out_size)
{
    const float* x     = (const float*)d_in[0];
    const float* Wr    = (const float*)d_in[1];
    const float* br    = (const float*)d_in[2];
    const float* Wi    = (const float*)d_in[3];
    const float* bi    = (const float*)d_in[4];
    const float* dwk   = (const float*)d_in[5];
    const float* dwb   = (const float*)d_in[6];
    const float* gamma = (const float*)d_in[7];
    const float* beta  = (const float*)d_in[8];
    const float* mmean = (const float*)d_in[9];
    const float* mvar  = (const float*)d_in[10];

    pre_kernel<<<16, 256>>>(Wr, Wi, br, bi, dwk, dwb, gamma, beta, mmean, mvar);
    fno_gemm_kernel<<<512, 128>>>(x);
    conv_resize_kernel<<<512, 128>>>((float*)d_out);
}

// round 13
// speedup vs baseline: 2.0760x; 1.3275x over previous
#include <cuda_runtime.h>
#include <math.h>
#include <stdint.h>

#define FIN 256
#define ND  16

// scratch (static device arrays — no allocations)
__device__ float g_A [FIN*ND];          // [k][n]
__device__ float g_c [ND];
__device__ float g_kw[9*ND];            // BN-folded depthwise weights [tap][d]
__device__ float g_kb[ND];              // BN-folded bias
__device__ float g_y [2*256*256*ND];    // intermediate y grid (8 MB)

__device__ __forceinline__ uint32_t smem_u32(const void* p) {
    uint32_t a;
    asm("{ .reg .u64 t; cvta.to.shared.u64 t, %1; cvt.u32.u64 %0, t; }"
        : "=r"(a) : "l"(p));
    return a;
}
__device__ __forceinline__ void cp_async16(uint32_t dst, const void* src) {
    asm volatile("cp.async.cg.shared.global [%0], [%1], 16;" :: "r"(dst), "l"(src));
}

// ---------------------------------------------------------------------------
// pre (fused, PARALLEL): grid 128 x 256 — one wave over the chip.
// Block bid owns k in {2*bid, 2*bid+1} = 32 (k,d) pairs.
// Phase 1: 8 threads per (k,d), each sums 32 strided m-terms of
//          G[k,d] = sum_m e^{-2pi i m k/256} (Wr[m,d] + i Wi[m,d]),
//          then 3-step shfl_down reduce (8-lane groups are warp-aligned).
// Phase 2: A[k,n] = (1/16) sum_d [Gr cos(2pi nd/16) - Gi sin(2pi nd/16)].
// Phase 3 (block 0): c[n], BN-folded conv weights/bias.
// ---------------------------------------------------------------------------
__global__ void __launch_bounds__(256) pre_kernel(const float* __restrict__ Wr,
                                                  const float* __restrict__ Wi,
                                                  const float* __restrict__ br,
                                                  const float* __restrict__ bi,
                                                  const float* __restrict__ dwk,
                                                  const float* __restrict__ dwb,
                                                  const float* __restrict__ gamma,
                                                  const float* __restrict__ beta,
                                                  const float* __restrict__ mmean,
                                                  const float* __restrict__ mvar)
{
    __shared__ float ct[256], st[256];
    __shared__ float gsr[32], gsi[32];   // block-local G: [kl*16 + d]
    int tid = threadIdx.x;
    {
        float ang = 6.283185307179586f * (float)tid / 256.0f;
        float s, c; sincosf(ang, &s, &c);
        ct[tid] = c; st[tid] = s;
    }
    __syncthreads();

    int pair = tid >> 3;                 // 0..31 : (kl, d)
    int r    = tid & 7;                  // m-slice
    int kl   = pair >> 4;                // 0..1
    int d    = pair & 15;
    int k    = blockIdx.x * 2 + kl;      // 0..255

    float grA = 0.f, giA = 0.f, grB = 0.f, giB = 0.f;
#pragma unroll
    for (int jj = 0; jj < 16; jj++) {
        int m0 = r + jj * 16;            // strided slices: r, r+16, ...
        int m1 = m0 + 8;
        int t0 = (m0 * k) & 255;
        int t1 = (m1 * k) & 255;
        float c0 = ct[t0], s0 = st[t0];
        float c1 = ct[t1], s1 = st[t1];
        float wr0 = Wr[m0 * 16 + d], wi0 = Wi[m0 * 16 + d];
        float wr1 = Wr[m1 * 16 + d], wi1 = Wi[m1 * 16 + d];
        grA = fmaf(c0, wr0, fmaf(s0, wi0, grA));
        giA = fmaf(c0, wi0, fmaf(-s0, wr0, giA));
        grB = fmaf(c1, wr1, fmaf(s1, wi1, grB));
        giB = fmaf(c1, wi1, fmaf(-s1, wr1, giB));
    }
    float gr = grA + grB;
    float gi = giA + giB;
    // reduce over the 8 m-slices (8-lane groups, warp-aligned)
#pragma unroll
    for (int off = 4; off > 0; off >>= 1) {
        gr += __shfl_down_sync(0xffffffffu, gr, off);
        gi += __shfl_down_sync(0xffffffffu, gi, off);
    }
    if (r == 0) { gsr[pair] = gr; gsi[pair] = gi; }
    __syncthreads();

    // Phase 2: 32 outputs (2 k x 16 n); cos(2pi u/16) = ct[u*16]
    if (tid < 32) {
        int kl2 = tid >> 4;
        int n   = tid & 15;
        float acc = 0.f;
#pragma unroll
        for (int dd = 0; dd < 16; dd++) {
            int u = ((n * dd) & 15) << 4;
            acc = fmaf(gsr[kl2 * 16 + dd], ct[u], fmaf(-gsi[kl2 * 16 + dd], st[u], acc));
        }
        g_A[(blockIdx.x * 2 + kl2) * 16 + n] = acc * 0.0625f;
    }

    // Phase 3: scalar folds (block 0, threads 32..191 — independent of G)
    if (blockIdx.x == 0 && tid >= 32 && tid < 192) {
        int tt = tid - 32;
        if (tt < 16) {
            float cc = 0.f;
#pragma unroll
            for (int dd = 0; dd < 16; dd++) {
                int u = ((tt * dd) & 15) << 4;
                cc += (br[dd] - bi[dd]) * ct[u] - (br[dd] + bi[dd]) * st[u];
            }
            g_c[tt] = cc * 0.0625f;
            float scale = gamma[tt] * rsqrtf(mvar[tt] + 1e-5f);
            g_kb[tt] = (dwb[tt] - mmean[tt]) * scale + beta[tt];
        }
        if (tt < 144) {
            int dd = tt & 15;
            float scale = gamma[dd] * rsqrtf(mvar[dd] + 1e-5f);
            g_kw[tt] = dwk[tt] * scale;
        }
    }
}

// ---------------------------------------------------------------------------
// main GEMM: y[patch, n] = A[n,:] . p + c[n]   (identical to best round R4)
// block = 128 threads = 4 warps; warp w owns 64 contiguous patches.
// Per-warp PRIVATE 2x4KB cp.async double-buffer -> no __syncthreads in the
// mainloop; per-row sync is wait_group + __syncwarp only.
// lane: cg = lane&3 (4 n-values), pg = lane>>2; patches p_local = jj*8+pg.
// XOR swizzle: chunk(p,c) stored at p*4 + (c ^ ((p>>1)&3)); read key (pg>>1)&3.
// Measured (R11 ncu): 32.8us = 100% scalar-FFMA-pipe rate.
// ---------------------------------------------------------------------------
__global__ void __launch_bounds__(128, 4) fno_gemm_kernel(const float* __restrict__ x)
{
    __shared__ float xs[4][2][1024];     // [warp][buf][64 patches * 16 floats]
    __shared__ float As[FIN * ND];       // A: [k][16]

    int t    = threadIdx.x;
    int w    = t >> 5;
    int lane = t & 31;
    int bid  = blockIdx.x;               // b*256 + ph
    int b    = bid >> 8;
    int ph   = bid & 255;

    // this warp's slice of the image row: 64 patches * 16 floats = 1024 floats
    const float* xbase = x + (size_t)(b * 4096 + ph * 16) * 4096 + w * 1024;

    uint32_t buf[2] = { smem_u32(&xs[w][0][0]), smem_u32(&xs[w][1][0]) };
    uint32_t dstoff[8];
#pragma unroll
    for (int it = 0; it < 8; it++) {
        int g4 = lane + it * 32;         // chunk index within warp slice 0..255
        int p  = g4 >> 2, c = g4 & 3;
        int cc = c ^ ((p >> 1) & 3);
        dstoff[it] = (uint32_t)((p * 4 + cc) << 4);
    }

    // kick off row 0
    {
        const char* src = (const char*)xbase;
#pragma unroll
        for (int it = 0; it < 8; it++)
            cp_async16(buf[0] + dstoff[it], src + ((lane + it * 32) << 4));
        asm volatile("cp.async.commit_group;");
    }

    {   // stage A into smem (4096 floats) — overlaps with row-0 cp.async
        const float4* A4  = (const float4*)g_A;
        float4*       As4 = (float4*)As;
#pragma unroll
        for (int it = 0; it < 8; it++)
            As4[t + it * 128] = A4[t + it * 128];
    }
    __syncthreads();                     // As visible to all warps (once, pre-loop)

    int cg  = lane & 3;
    int pg  = lane >> 2;                 // 0..7
    int swz = (pg >> 1) & 3;             // read-side swizzle key
    float4 acc[8];
#pragma unroll
    for (int jj = 0; jj < 8; jj++) acc[jj] = make_float4(0.f, 0.f, 0.f, 0.f);

    for (int kr = 0; kr < 16; kr++) {
        if (kr < 15) {
            uint32_t dbuf = buf[(kr + 1) & 1];
            const char* src = (const char*)(xbase + (size_t)(kr + 1) * 4096);
#pragma unroll
            for (int it = 0; it < 8; it++)
                cp_async16(dbuf + dstoff[it], src + ((lane + it * 32) << 4));
            asm volatile("cp.async.commit_group;");
            asm volatile("cp.async.wait_group 1;");   // row kr landed
        } else {
            asm volatile("cp.async.wait_group 0;");
        }
        __syncwarp();                    // all lanes' chunks of row kr visible

        const float* xb = xs[w][kr & 1];
#pragma unroll
        for (int kc4 = 0; kc4 < 4; kc4++) {
            int k0 = kr * 16 + kc4 * 4;
            const float* Ab = &As[k0 * 16 + cg * 4];
            float4 A0 = *(const float4*)(Ab);
            float4 A1 = *(const float4*)(Ab + 16);
            float4 A2 = *(const float4*)(Ab + 32);
            float4 A3 = *(const float4*)(Ab + 48);
            int co = (kc4 ^ swz) << 2;   // swizzled float offset within patch
#pragma unroll
            for (int jj = 0; jj < 8; jj++) {
                int p = jj * 8 + pg;     // local patch 0..63
                float4 xv = *(const float4*)&xb[p * 16 + co];
                acc[jj].x = fmaf(xv.x, A0.x, fmaf(xv.y, A1.x, fmaf(xv.z, A2.x, fmaf(xv.w, A3.x, acc[jj].x))));
                acc[jj].y = fmaf(xv.x, A0.y, fmaf(xv.y, A1.y, fmaf(xv.z, A2.y, fmaf(xv.w, A3.y, acc[jj].y))));
                acc[jj].z = fmaf(xv.x, A0.z, fmaf(xv.y, A1.z, fmaf(xv.z, A2.z, fmaf(xv.w, A3.z, acc[jj].z))));
                acc[jj].w = fmaf(xv.x, A0.w, fmaf(xv.y, A1.w, fmaf(xv.z, A2.w, fmaf(xv.w, A3.w, acc[jj].w))));
            }
        }
        __syncwarp();                    // buffer (kr&1) free before re-issue at kr+1
    }

    float4 cc = ((const float4*)g_c)[cg];
    float4* y4 = (float4*)g_y;
#pragma unroll
    for (int jj = 0; jj < 8; jj++) {
        int gp = bid * 256 + w * 64 + jj * 8 + pg;   // global patch
        float4 o = acc[jj];
        o.x += cc.x; o.y += cc.y; o.z += cc.z; o.w += cc.w;
        y4[gp * 4 + cg] = o;
    }
}

// ---------------------------------------------------------------------------
// depthwise 3x3 SAME conv (BN folded) at resized positions.
// Two vertical outputs per thread: i = 2*iq and 2*iq+1 share row 4*iq+2.
// ---------------------------------------------------------------------------
__global__ void __launch_bounds__(128) conv_resize_kernel(float* __restrict__ out)
{
    int lin = blockIdx.x * 128 + threadIdx.x;   // 0..65535
    int cg = lin & 3;
    int j  = (lin >> 2) & 127;
    int iq = (lin >> 9) & 63;
    int b  = lin >> 15;

    int i0 = 2 * iq;
    int c1 = 2 * j + 1;
    int rbase = 4 * iq;                          // = (2*i0+1) - 1

    const float4* y4  = (const float4*)g_y;
    const float4* kw4 = (const float4*)g_kw;
    float4 kb = ((const float4*)g_kb)[cg];
    float4 s0 = kb, s1 = kb;

#pragma unroll
    for (int rr = 0; rr < 5; rr++) {
        int r = rbase + rr;
        if (r > 255) continue;                   // only rr=4 at iq=63
#pragma unroll
        for (int dx = -1; dx <= 1; dx++) {
            int c = c1 + dx;                     // c >= 0 always
            if (c > 255) continue;
            float4 v = y4[((b * 256 + r) * 256 + c) * 4 + cg];
            if (rr < 3) {                        // output i0: taps rows rr=0,1,2
                float4 w = kw4[(rr * 3 + (dx + 1)) * 4 + cg];
                s0.x = fmaf(v.x, w.x, s0.x);
                s0.y = fmaf(v.y, w.y, s0.y);
                s0.z = fmaf(v.z, w.z, s0.z);
                s0.w = fmaf(v.w, w.w, s0.w);
            }
            if (rr >= 2) {                       // output i0+1: taps rows rr=2,3,4
                float4 w = kw4[((rr - 2) * 3 + (dx + 1)) * 4 + cg];
                s1.x = fmaf(v.x, w.x, s1.x);
                s1.y = fmaf(v.y, w.y, s1.y);
                s1.z = fmaf(v.z, w.z, s1.z);
                s1.w = fmaf(v.w, w.w, s1.w);
            }
        }
    }
    float4* o4 = (float4*)out;
    o4[((b * 128 + i0) * 128 + j) * 4 + cg]       = s0;
    o4[((b * 128 + i0 + 1) * 128 + j) * 4 + cg]   = s1;
}

// ---------------------------------------------------------------------------
extern "C" void kernel_launch(void* const* d_in, const int* in_sizes, int n_in,
                              void* d_out, int out_size)
{
    const float* x     = (const float*)d_in[0];
    const float* Wr    = (const float*)d_in[1];
    const float* br    = (const float*)d_in[2];
    const float* Wi    = (const float*)d_in[3];
    const float* bi    = (const float*)d_in[4];
    const float* dwk   = (const float*)d_in[5];
    const float* dwb   = (const float*)d_in[6];
    const float* gamma = (const float*)d_in[7];
    const float* beta  = (const float*)d_in[8];
    const float* mmean = (const float*)d_in[9];
    const float* mvar  = (const float*)d_in[10];

    pre_kernel<<<128, 256>>>(Wr, Wi, br, bi, dwk, dwb, gamma, beta, mmean, mvar);
    fno_gemm_kernel<<<512, 128>>>(x);
    conv_resize_kernel<<<512, 128>>>((float*)d_out);
}

// round 14
// speedup vs baseline: 2.0852x; 1.0044x over previous
#include <cuda_runtime.h>
#include <math.h>
#include <stdint.h>

#define FIN 256
#define ND  16

// scratch (static device arrays — no allocations)
__device__ float g_A [FIN*ND];          // [k][n]
__device__ float g_c [ND];
__device__ float g_kw[9*ND];            // BN-folded depthwise weights [tap][d]
__device__ float g_kb[ND];              // BN-folded bias
__device__ float g_y [2*256*256*ND];    // intermediate y grid (8 MB)

__device__ __forceinline__ uint32_t smem_u32(const void* p) {
    uint32_t a;
    asm("{ .reg .u64 t; cvta.to.shared.u64 t, %1; cvt.u32.u64 %0, t; }"
        : "=r"(a) : "l"(p));
    return a;
}
__device__ __forceinline__ void cp_async16(uint32_t dst, const void* src) {
    asm volatile("cp.async.cg.shared.global [%0], [%1], 16;" :: "r"(dst), "l"(src));
}
// packed dual-FMA (SASS FFMA2): d.lo += a.lo*b.lo ; d.hi += a.hi*b.hi
__device__ __forceinline__ void ffma2(unsigned long long& d,
                                      unsigned long long a,
                                      unsigned long long b) {
    asm("fma.rn.f32x2 %0, %1, %2, %0;" : "+l"(d) : "l"(a), "l"(b));
}
// duplicate a scalar into both f32x2 lanes (one MOV, alu pipe)
__device__ __forceinline__ unsigned long long dup2(float v) {
    unsigned long long r;
    asm("mov.b64 %0, {%1, %1};" : "=l"(r) : "f"(v));
    return r;
}
__device__ __forceinline__ float2 u2f2(unsigned long long u) {
    float2 f;
    asm("mov.b64 {%0, %1}, %2;" : "=f"(f.x), "=f"(f.y) : "l"(u));
    return f;
}

// ---------------------------------------------------------------------------
// pre (fused, parallel): grid 128 x 256 — unchanged from R13.
// ---------------------------------------------------------------------------
__global__ void __launch_bounds__(256) pre_kernel(const float* __restrict__ Wr,
                                                  const float* __restrict__ Wi,
                                                  const float* __restrict__ br,
                                                  const float* __restrict__ bi,
                                                  const float* __restrict__ dwk,
                                                  const float* __restrict__ dwb,
                                                  const float* __restrict__ gamma,
                                                  const float* __restrict__ beta,
                                                  const float* __restrict__ mmean,
                                                  const float* __restrict__ mvar)
{
    __shared__ float ct[256], st[256];
    __shared__ float gsr[32], gsi[32];   // block-local G: [kl*16 + d]
    int tid = threadIdx.x;
    {
        float ang = 6.283185307179586f * (float)tid / 256.0f;
        float s, c; sincosf(ang, &s, &c);
        ct[tid] = c; st[tid] = s;
    }
    __syncthreads();

    int pair = tid >> 3;                 // 0..31 : (kl, d)
    int r    = tid & 7;                  // m-slice
    int kl   = pair >> 4;                // 0..1
    int d    = pair & 15;
    int k    = blockIdx.x * 2 + kl;      // 0..255

    float grA = 0.f, giA = 0.f, grB = 0.f, giB = 0.f;
#pragma unroll
    for (int jj = 0; jj < 16; jj++) {
        int m0 = r + jj * 16;            // strided slices: r, r+16, ...
        int m1 = m0 + 8;
        int t0 = (m0 * k) & 255;
        int t1 = (m1 * k) & 255;
        float c0 = ct[t0], s0 = st[t0];
        float c1 = ct[t1], s1 = st[t1];
        float wr0 = Wr[m0 * 16 + d], wi0 = Wi[m0 * 16 + d];
        float wr1 = Wr[m1 * 16 + d], wi1 = Wi[m1 * 16 + d];
        grA = fmaf(c0, wr0, fmaf(s0, wi0, grA));
        giA = fmaf(c0, wi0, fmaf(-s0, wr0, giA));
        grB = fmaf(c1, wr1, fmaf(s1, wi1, grB));
        giB = fmaf(c1, wi1, fmaf(-s1, wr1, giB));
    }
    float gr = grA + grB;
    float gi = giA + giB;
#pragma unroll
    for (int off = 4; off > 0; off >>= 1) {
        gr += __shfl_down_sync(0xffffffffu, gr, off);
        gi += __shfl_down_sync(0xffffffffu, gi, off);
    }
    if (r == 0) { gsr[pair] = gr; gsi[pair] = gi; }
    __syncthreads();

    if (tid < 32) {
        int kl2 = tid >> 4;
        int n   = tid & 15;
        float acc = 0.f;
#pragma unroll
        for (int dd = 0; dd < 16; dd++) {
            int u = ((n * dd) & 15) << 4;
            acc = fmaf(gsr[kl2 * 16 + dd], ct[u], fmaf(-gsi[kl2 * 16 + dd], st[u], acc));
        }
        g_A[(blockIdx.x * 2 + kl2) * 16 + n] = acc * 0.0625f;
    }

    if (blockIdx.x == 0 && tid >= 32 && tid < 192) {
        int tt = tid - 32;
        if (tt < 16) {
            float cc = 0.f;
#pragma unroll
            for (int dd = 0; dd < 16; dd++) {
                int u = ((tt * dd) & 15) << 4;
                cc += (br[dd] - bi[dd]) * ct[u] - (br[dd] + bi[dd]) * st[u];
            }
            g_c[tt] = cc * 0.0625f;
            float scale = gamma[tt] * rsqrtf(mvar[tt] + 1e-5f);
            g_kb[tt] = (dwb[tt] - mmean[tt]) * scale + beta[tt];
        }
        if (tt < 144) {
            int dd = tt & 15;
            float scale = gamma[dd] * rsqrtf(mvar[dd] + 1e-5f);
            g_kw[tt] = dwk[tt] * scale;
        }
    }
}

// ---------------------------------------------------------------------------
// main GEMM: y[patch, n] = A[n,:] . p + c[n]
// R4 structure (warp-private cp.async double-buffer, XOR swizzle, no block
// barriers) with FFMA2 inner loop paired over n:
//   acc[jj][np] (f32x2) accumulates (y[n0], y[n1]); A pairs are adjacent in
//   the row-major As tile; x scalars duplicated via one mov.b64 each.
// Per-n summation order identical to the scalar version -> same rel_err.
// FMA-pipe ops per jj*kc4: 8 FFMA2 (was 16 FFMA); acc regs unchanged (32).
// ---------------------------------------------------------------------------
__global__ void __launch_bounds__(128, 4) fno_gemm_kernel(const float* __restrict__ x)
{
    __shared__ float xs[4][2][1024];     // [warp][buf][64 patches * 16 floats]
    __shared__ float As[FIN * ND];       // A: [k][16]

    int t    = threadIdx.x;
    int w    = t >> 5;
    int lane = t & 31;
    int bid  = blockIdx.x;               // b*256 + ph
    int b    = bid >> 8;
    int ph   = bid & 255;

    // this warp's slice of the image row: 64 patches * 16 floats = 1024 floats
    const float* xbase = x + (size_t)(b * 4096 + ph * 16) * 4096 + w * 1024;

    uint32_t buf[2] = { smem_u32(&xs[w][0][0]), smem_u32(&xs[w][1][0]) };
    uint32_t dstoff[8];
#pragma unroll
    for (int it = 0; it < 8; it++) {
        int g4 = lane + it * 32;         // chunk index within warp slice 0..255
        int p  = g4 >> 2, c = g4 & 3;
        int cc = c ^ ((p >> 1) & 3);
        dstoff[it] = (uint32_t)((p * 4 + cc) << 4);
    }

    // kick off row 0
    {
        const char* src = (const char*)xbase;
#pragma unroll
        for (int it = 0; it < 8; it++)
            cp_async16(buf[0] + dstoff[it], src + ((lane + it * 32) << 4));
        asm volatile("cp.async.commit_group;");
    }

    {   // stage A into smem (4096 floats) — overlaps with row-0 cp.async
        const float4* A4  = (const float4*)g_A;
        float4*       As4 = (float4*)As;
#pragma unroll
        for (int it = 0; it < 8; it++)
            As4[t + it * 128] = A4[t + it * 128];
    }
    __syncthreads();                     // As visible to all warps (once, pre-loop)

    int cg  = lane & 3;
    int pg  = lane >> 2;                 // 0..7
    int swz = (pg >> 1) & 3;             // read-side swizzle key
    unsigned long long acc[8][2];        // [patch][n-pair] f32x2
#pragma unroll
    for (int jj = 0; jj < 8; jj++) { acc[jj][0] = 0ull; acc[jj][1] = 0ull; }

    for (int kr = 0; kr < 16; kr++) {
        if (kr < 15) {
            uint32_t dbuf = buf[(kr + 1) & 1];
            const char* src = (const char*)(xbase + (size_t)(kr + 1) * 4096);
#pragma unroll
            for (int it = 0; it < 8; it++)
                cp_async16(dbuf + dstoff[it], src + ((lane + it * 32) << 4));
            asm volatile("cp.async.commit_group;");
            asm volatile("cp.async.wait_group 1;");   // row kr landed
        } else {
            asm volatile("cp.async.wait_group 0;");
        }
        __syncwarp();                    // all lanes' chunks of row kr visible

        const float* xb = xs[w][kr & 1];
#pragma unroll
        for (int kc4 = 0; kc4 < 4; kc4++) {
            int k0 = kr * 16 + kc4 * 4;
            const float* Ab = &As[k0 * 16 + cg * 4];
            // A rows k0..k0+3, 4 floats each = 2 f32x2 pairs {(n0,n1),(n2,n3)}
            ulonglong2 A0 = *(const ulonglong2*)(Ab);
            ulonglong2 A1 = *(const ulonglong2*)(Ab + 16);
            ulonglong2 A2 = *(const ulonglong2*)(Ab + 32);
            ulonglong2 A3 = *(const ulonglong2*)(Ab + 48);
            int co = (kc4 ^ swz) << 2;   // swizzled float offset within patch
#pragma unroll
            for (int jj = 0; jj < 8; jj++) {
                int p = jj * 8 + pg;     // local patch 0..63
                float4 xv = *(const float4*)&xb[p * 16 + co];
                unsigned long long x0 = dup2(xv.x);
                unsigned long long x1 = dup2(xv.y);
                unsigned long long x2 = dup2(xv.z);
                unsigned long long x3 = dup2(xv.w);
                ffma2(acc[jj][0], x0, A0.x); ffma2(acc[jj][1], x0, A0.y);
                ffma2(acc[jj][0], x1, A1.x); ffma2(acc[jj][1], x1, A1.y);
                ffma2(acc[jj][0], x2, A2.x); ffma2(acc[jj][1], x2, A2.y);
                ffma2(acc[jj][0], x3, A3.x); ffma2(acc[jj][1], x3, A3.y);
            }
        }
        __syncwarp();                    // buffer (kr&1) free before re-issue at kr+1
    }

    float4 cc = ((const float4*)g_c)[cg];
    float4* y4 = (float4*)g_y;
#pragma unroll
    for (int jj = 0; jj < 8; jj++) {
        int gp = bid * 256 + w * 64 + jj * 8 + pg;   // global patch
        float2 p01 = u2f2(acc[jj][0]);
        float2 p23 = u2f2(acc[jj][1]);
        float4 o;
        o.x = p01.x + cc.x;
        o.y = p01.y + cc.y;
        o.z = p23.x + cc.z;
        o.w = p23.y + cc.w;
        y4[gp * 4 + cg] = o;
    }
}

// ---------------------------------------------------------------------------
// depthwise 3x3 SAME conv (BN folded) at resized positions.
// One output per thread (131072 threads) — 2x parallelism vs R13 to cover
// L2 latency (was occ 20%, issue 7.5%).
// ---------------------------------------------------------------------------
__global__ void __launch_bounds__(128) conv_resize_kernel(float* __restrict__ out)
{
    int lin = blockIdx.x * 128 + threadIdx.x;   // 0..131071
    int cg = lin & 3;
    int j  = (lin >> 2) & 127;
    int i  = (lin >> 9) & 127;
    int b  = lin >> 16;

    int r1 = 2 * i + 1;
    int c1 = 2 * j + 1;

    const float4* y4  = (const float4*)g_y;
    const float4* kw4 = (const float4*)g_kw;
    float4 kb = ((const float4*)g_kb)[cg];
    float sx = kb.x, sy = kb.y, sz = kb.z, sw = kb.w;

#pragma unroll
    for (int dy = -1; dy <= 1; dy++) {
        int r = r1 + dy;                         // r >= 0 always
        if (r > 255) continue;
#pragma unroll
        for (int dx = -1; dx <= 1; dx++) {
            int c = c1 + dx;                     // c >= 0 always
            if (c > 255) continue;
            float4 v = y4[((b * 256 + r) * 256 + c) * 4 + cg];
            float4 w = kw4[((dy + 1) * 3 + (dx + 1)) * 4 + cg];
            sx = fmaf(v.x, w.x, sx);
            sy = fmaf(v.y, w.y, sy);
            sz = fmaf(v.z, w.z, sz);
            sw = fmaf(v.w, w.w, sw);
        }
    }
    ((float4*)out)[((b * 128 + i) * 128 + j) * 4 + cg] = make_float4(sx, sy, sz, sw);
}

// ---------------------------------------------------------------------------
extern "C" void kernel_launch(void* const* d_in, const int* in_sizes, int n_in,
                              void* d_out, int out_size)
{
    const float* x     = (const float*)d_in[0];
    const float* Wr    = (const float*)d_in[1];
    const float* br    = (const float*)d_in[2];
    const float* Wi    = (const float*)d_in[3];
    const float* bi    = (const float*)d_in[4];
    const float* dwk   = (const float*)d_in[5];
    const float* dwb   = (const float*)d_in[6];
    const float* gamma = (const float*)d_in[7];
    const float* beta  = (const float*)d_in[8];
    const float* mmean = (const float*)d_in[9];
    const float* mvar  = (const float*)d_in[10];

    pre_kernel<<<128, 256>>>(Wr, Wi, br, bi, dwk, dwb, gamma, beta, mmean, mvar);
    fno_gemm_kernel<<<512, 128>>>(x);
    conv_resize_kernel<<<1024, 128>>>((float*)d_out);
}